// round 12
// baseline (speedup 1.0000x reference)
#include <cuda_runtime.h>
#include <cuda_bf16.h>
#include <cstdint>
#include <cstddef>

// Problem constants
#define BATCH   4
#define SEQ     2048
#define DMODEL  512
#define NHEADS  8
#define HDIM    64
#define DFF     2048
#define NLAYERS 6
#define MROWS   (BATCH * SEQ)            // 8192

// -------- scratch (device globals; no allocation allowed) --------
__device__ float g_x   [MROWS * DMODEL];   // fp32 residual stream
__device__ float g_xr  [MROWS * DMODEL];   // tf32-rounded copy (gemm A input)
__device__ float g_q   [MROWS * DMODEL];
__device__ float g_k   [MROWS * DMODEL];
__device__ float g_v   [MROWS * DMODEL];
__device__ float g_attn[MROWS * DMODEL];
__device__ float g_tmp [MROWS * DMODEL];
__device__ float g_ff  [MROWS * DFF];
// tf32-rounded weights in tiled pair-permuted layout (17/16 padding)
#define WR_TOTAL 20054016
__device__ float g_wr  [WR_TOTAL];

// ==================== helpers ====================
__device__ __forceinline__ uint32_t f2tf32(float x) {
    uint32_t u;
    asm("cvt.rna.tf32.f32 %0, %1;" : "=r"(u) : "f"(x));
    return u;
}
__device__ __forceinline__ float rnd_tf32(float x) {
    return __uint_as_float(f2tf32(x));
}
__device__ __forceinline__ uint4 cvt4(float4 v) {
    return make_uint4(f2tf32(v.x), f2tf32(v.y), f2tf32(v.z), f2tf32(v.w));
}
__device__ __forceinline__ float ex2f(float x) {
    float y;
    asm("ex2.approx.f32 %0, %1;" : "=f"(y) : "f"(x));
    return y;
}
__device__ __forceinline__ uint32_t smem_u32(const void* p) {
    uint32_t a;
    asm("{ .reg .u64 t; cvta.to.shared.u64 t, %1; cvt.u32.u64 %0, t; }"
        : "=r"(a) : "l"(p));
    return a;
}
__device__ __forceinline__ void cp16(uint32_t dst, const void* src) {
    asm volatile("cp.async.cg.shared.global [%0], [%1], 16;"
                 :: "r"(dst), "l"(src));
}
#define CP_COMMIT() asm volatile("cp.async.commit_group;" ::: "memory")
#define CP_WAIT0()  asm volatile("cp.async.wait_group 0;" ::: "memory")
#define CP_WAIT1()  asm volatile("cp.async.wait_group 1;" ::: "memory")

// mma.sync m16n8k8 tf32: d = a*b + c  (f32 accum)
__device__ __forceinline__ void mma_tf32(
    float* d, const uint32_t* a, const uint32_t* b, const float* c)
{
    asm volatile(
        "mma.sync.aligned.m16n8k8.row.col.f32.tf32.tf32.f32 "
        "{%0,%1,%2,%3}, {%4,%5,%6,%7}, {%8,%9}, {%10,%11,%12,%13};"
        : "=f"(d[0]), "=f"(d[1]), "=f"(d[2]), "=f"(d[3])
        : "r"(a[0]), "r"(a[1]), "r"(a[2]), "r"(a[3]),
          "r"(b[0]), "r"(b[1]),
          "f"(c[0]), "f"(c[1]), "f"(c[2]), "f"(c[3]));
}

// =====================================================================
// Weight pass: fp32 -> tf32(rna) into TILED PAIR-PERMUTED layout.
// Tile = 32k x 128n -> 4352 words:
//   word = 2*(17*n + 4*(k%4) + k/8) + (k%8)/4   (17th pair per n = pad 0)
// One launch covers all 6 tensors (z), all layers (y), tiles (x).
// =====================================================================
__global__ void __launch_bounds__(256) round_all_kernel(
    const float* __restrict__ s0, const float* __restrict__ s1,
    const float* __restrict__ s2, const float* __restrict__ s3,
    const float* __restrict__ s4, const float* __restrict__ s5,
    float* __restrict__ wr)
{
    int t = blockIdx.z;
    const float* s;
    if (t == 0) s = s0; else if (t == 1) s = s1; else if (t == 2) s = s2;
    else if (t == 3) s = s3; else if (t == 4) s = s4; else s = s5;
    int K = (t == 5) ? 2048 : 512;
    int N = (t == 4) ? 2048 : 512;
    int ntn = N >> 7;
    int tiles = (K >> 5) * ntn;
    int bx = blockIdx.x;
    if (bx >= tiles) return;
    const size_t dseg[6] = {0, 1671168, 3342336, 5013504, 6684672, 13369344};
    int kt = bx / ntn, nt = bx % ntn;
    const float* sl = s + (size_t)blockIdx.y * K * N;
    float* d = wr + dseg[t] + (size_t)blockIdx.y * tiles * 4352
                 + (size_t)bx * 4352;
    for (int w = threadIdx.x; w < 4352; w += 256) {
        int p = w >> 1, h = w & 1;
        int n = p / 17, q = p - n * 17;
        float val = 0.f;
        if (q < 16) {
            int c = q >> 2, ks = q & 3;
            int k = ks * 8 + c + 4 * h;
            val = sl[(size_t)(kt * 32 + k) * N + nt * 128 + n];
        }
        d[w] = rnd_tf32(val);
    }
}

// =====================================================================
// Embedding + positional encoding: dual write (fp32 + rounded)
// =====================================================================
__global__ void __launch_bounds__(128) embed_kernel(
    const int* __restrict__ src, const float* __restrict__ emb,
    const float* __restrict__ pe, float* __restrict__ xf,
    float* __restrict__ xr)
{
    int bl  = blockIdx.x;
    int l   = bl & (SEQ - 1);
    int tok = src[bl];
    int c   = threadIdx.x * 4;
    float4 e = *(const float4*)(emb + (size_t)tok * DMODEL + c);
    float4 p = *(const float4*)(pe  + (size_t)l   * DMODEL + c);
    float4 o; o.x = e.x + p.x; o.y = e.y + p.y; o.z = e.z + p.z; o.w = e.w + p.w;
    *(float4*)(xf + (size_t)bl * DMODEL + c) = o;
    *(uint4*)(xr + (size_t)bl * DMODEL + c) = cvt4(o);
}

// =====================================================================
// Tensor-core GEMM (tf32 mma.sync): C = A@W + bias (+res)(+relu)(+rnd)
// A pre-rounded row-major (cp.async, [128][36]); W in tiled pair-
// permuted layout -> B fragments via conflict-free LDS.64.
// CTA 128x128, 8 warps (2x4, warp tile 64x32), KC=32, 3-stage pipeline.
// permN: permute output d-columns within 8-groups (for Q/K only).
// =====================================================================
#define KC3    32
#define AW     36
#define A_STG  (128 * AW)                 // 4608 words
#define B_STG  4352                       // one permuted tile
#define STG_W  (A_STG + B_STG)            // 8960 words
#define GS3_SMEM (3 * STG_W * 4)          // 107520 bytes

__device__ __forceinline__ void gemm_body(
    const float* __restrict__ A, const float* __restrict__ Wp,
    const float* __restrict__ bias, const float* __restrict__ res,
    float* __restrict__ C, int M, int N, int K, int relu, int rnd,
    int permN, int bxx, int byy)
{
    extern __shared__ uint32_t sm[];
    uint32_t sbase = smem_u32(sm);

    int tid  = threadIdx.x;
    int lane = tid & 31;
    int wid  = tid >> 5;
    int bm = byy << 7, bn = bxx << 7;
    int warpM = (wid >> 2) * 64;
    int warpN = (wid & 3) * 32;
    int r0 = lane >> 2, c0 = lane & 3;
    int bntiles = N >> 7;

    int aRow[4], aC16[4];
#pragma unroll
    for (int i = 0; i < 4; i++) {
        int id = tid + i * 256;
        aRow[i] = id >> 3;  aC16[i] = id & 7;
    }

    float acc[4][4][4];
#pragma unroll
    for (int mt = 0; mt < 4; mt++)
#pragma unroll
        for (int nt = 0; nt < 4; nt++)
#pragma unroll
            for (int r = 0; r < 4; r++) acc[mt][nt][r] = 0.f;

    int nst = K / KC3;

    auto issue_stage = [&](int st, int kc) {
        uint32_t aB = sbase + (st * STG_W) * 4;
        uint32_t bB = sbase + (st * STG_W + A_STG) * 4;
#pragma unroll
        for (int i = 0; i < 4; i++)
            cp16(aB + (aRow[i] * AW + aC16[i] * 4) * 4,
                 A + (size_t)(bm + aRow[i]) * K + kc + aC16[i] * 4);
        const float* tsrc = Wp + ((size_t)(kc >> 5) * bntiles + bxx) * 4352;
#pragma unroll
        for (int i = 0; i < 4; i++) {
            int id = tid + i * 256;
            cp16(bB + id * 16, tsrc + id * 4);
        }
        if (tid < 64) {
            int id = 1024 + tid;
            cp16(bB + id * 16, tsrc + id * 4);
        }
        CP_COMMIT();
    };

    issue_stage(0, 0);
    issue_stage(1, KC3);

    for (int s = 0; s < nst; s++) {
        int cur = s % 3;
        if (s + 1 < nst) CP_WAIT1(); else CP_WAIT0();
        __syncthreads();
        if (s + 2 < nst) issue_stage((s + 2) % 3, (s + 2) * KC3);

        const uint32_t* Ab = sm + cur * STG_W;
        const uint32_t* Bb = Ab + A_STG;
#pragma unroll
        for (int ks = 0; ks < 4; ks++) {
            int k0 = ks * 8 + c0;
            uint32_t af[4][4], bf[4][2];
#pragma unroll
            for (int mt = 0; mt < 4; mt++) {
                int m0 = warpM + mt * 16 + r0;
                af[mt][0] = Ab[m0 * AW + k0];
                af[mt][1] = Ab[(m0 + 8) * AW + k0];
                af[mt][2] = Ab[m0 * AW + k0 + 4];
                af[mt][3] = Ab[(m0 + 8) * AW + k0 + 4];
            }
#pragma unroll
            for (int nt = 0; nt < 4; nt++) {
                int n0 = warpN + nt * 8 + r0;
                uint2 bp = *(const uint2*)&Bb[2 * (17 * n0 + 4 * c0 + ks)];
                bf[nt][0] = bp.x;
                bf[nt][1] = bp.y;
            }
#pragma unroll
            for (int mt = 0; mt < 4; mt++)
#pragma unroll
                for (int nt = 0; nt < 4; nt++)
                    mma_tf32(acc[mt][nt], af[mt], bf[nt], acc[mt][nt]);
        }
        __syncthreads();
    }

#pragma unroll
    for (int mt = 0; mt < 4; mt++) {
        int row0 = bm + warpM + mt * 16 + r0;
#pragma unroll
        for (int h = 0; h < 2; h++) {
            int row = row0 + h * 8;
            float* crow = C + (size_t)row * N;
            const float* rrow = res ? (res + (size_t)row * N) : nullptr;
#pragma unroll
            for (int nt = 0; nt < 4; nt++) {
                int col = bn + warpN + nt * 8 + 2 * c0;
                float2 b2 = *(const float2*)(bias + col);
                float2 o;
                o.x = acc[mt][nt][h * 2 + 0] + b2.x;
                o.y = acc[mt][nt][h * 2 + 1] + b2.y;
                if (rrow) {
                    float2 r2 = *(const float2*)(rrow + col);
                    o.x += r2.x; o.y += r2.y;
                }
                if (relu) { o.x = fmaxf(o.x, 0.f); o.y = fmaxf(o.y, 0.f); }
                if (rnd)  { o.x = rnd_tf32(o.x);   o.y = rnd_tf32(o.y); }
                if (permN) {
                    // permute within 8-col group: k -> 2*(k%4) + k/4
                    int colb = bn + warpN + nt * 8;
                    int k1 = 2 * c0, k2 = 2 * c0 + 1;
                    crow[colb + ((k1 & 3) * 2 + (k1 >> 2))] = o.x;
                    crow[colb + ((k2 & 3) * 2 + (k2 >> 2))] = o.y;
                } else {
                    *(float2*)(crow + col) = o;
                }
            }
        }
    }
}

__global__ void __launch_bounds__(256, 2) gemm_mma(
    const float* __restrict__ A, const float* __restrict__ Wp,
    const float* __restrict__ bias, const float* __restrict__ res,
    float* __restrict__ C, int M, int N, int K, int relu, int rnd)
{
    gemm_body(A, Wp, bias, res, C, M, N, K, relu, rnd, 0,
              blockIdx.x, blockIdx.y);
}

// fused QKV: z selects weight/bias/output. q,k outputs are d-permuted
// (pairs (k,k+4) adjacent) for LDS.64 fragments in attention; v is not.
__global__ void __launch_bounds__(256, 2) gemm_qkv(
    const float* __restrict__ x,
    const float* __restrict__ Wq, const float* __restrict__ Wk,
    const float* __restrict__ Wv,
    const float* __restrict__ bq, const float* __restrict__ bk,
    const float* __restrict__ bv,
    float* __restrict__ q, float* __restrict__ k, float* __restrict__ v)
{
    const float* W; const float* bias; float* C; int permN;
    if (blockIdx.z == 0)      { W = Wq; bias = bq; C = q; permN = 1; }
    else if (blockIdx.z == 1) { W = Wk; bias = bk; C = k; permN = 1; }
    else                      { W = Wv; bias = bv; C = v; permN = 0; }
    gemm_body(x, W, bias, nullptr, C, MROWS, DMODEL, DMODEL, 0, 1, permN,
              blockIdx.x, blockIdx.y);
}

// =====================================================================
// Tensor-core flash attention (tf32 mma.sync) — round-9 structure with
// pair-permuted Q/K (LDS.64 fragments in the S phase). V/P unchanged.
// smem: Q | P | K0 | V0 | K1 | V1, each 64x68 words.
// =====================================================================
#define ATS 68
#define TILE_W (64 * ATS)                 // 4352 words
#define ATTN3_SMEM (6 * TILE_W * 4)       // 104448 bytes
#define SCALE_LOG2E 0.1803368801111204f   // 0.125 * log2(e)

__device__ __forceinline__ void cp_tile(
    uint32_t dstbase, const float* __restrict__ g, int tid)
{
#pragma unroll
    for (int i = 0; i < 8; i++) {
        int id  = tid + i * 128;
        int row = id >> 4, c16 = id & 15;
        cp16(dstbase + (row * ATS + c16 * 4) * 4, g + row * 64 + c16 * 4);
    }
}

__global__ void __launch_bounds__(128, 2) attn_mma(
    const float* __restrict__ q, const float* __restrict__ k,
    const float* __restrict__ v, float* __restrict__ out)
{
    extern __shared__ uint32_t smu[];
    uint32_t sbase = smem_u32(smu);
    uint32_t* Qs = smu;
    uint32_t* Ps = smu + TILE_W;

    int tid  = threadIdx.x;
    int lane = tid & 31;
    int wid  = tid >> 5;
    int bh   = blockIdx.y;
    int qt   = blockIdx.x;
    int b    = bh >> 3, h = bh & 7;

    const float* Qg = q + ((size_t)bh * SEQ + qt * 64) * HDIM;
    const float* Kg = k + (size_t)bh * SEQ * HDIM;
    const float* Vg = v + (size_t)bh * SEQ * HDIM;

    cp_tile(sbase, Qg, tid);
    cp_tile(sbase + (2 * TILE_W) * 4, Kg, tid);
    cp_tile(sbase + (3 * TILE_W) * 4, Vg, tid);
    CP_COMMIT();

    int warpM = wid * 16;
    int r0 = lane >> 2, c0 = lane & 3;

    float m0 = -1e30f, m1 = -1e30f, l0 = 0.f, l1 = 0.f;
    float o_acc[8][4];
#pragma unroll
    for (int nt = 0; nt < 8; nt++)
#pragma unroll
        for (int r = 0; r < 4; r++) o_acc[nt][r] = 0.f;

    for (int kt = 0; kt < SEQ / 64; kt++) {
        int cur = kt & 1, nb = cur ^ 1;
        CP_WAIT0();
        __syncthreads();
        if (kt + 1 < SEQ / 64) {
            cp_tile(sbase + ((2 + 2 * nb) * TILE_W) * 4,
                    Kg + (size_t)(kt + 1) * 64 * HDIM, tid);
            cp_tile(sbase + ((3 + 2 * nb) * TILE_W) * 4,
                    Vg + (size_t)(kt + 1) * 64 * HDIM, tid);
            CP_COMMIT();
        }
        const uint32_t* Ks = smu + (2 + 2 * cur) * TILE_W;
        const uint32_t* Vs = smu + (3 + 2 * cur) * TILE_W;

        // ---- S = Q K^T (pair-permuted Q/K -> LDS.64 fragments) ----
        float sacc[8][4];
#pragma unroll
        for (int nt = 0; nt < 8; nt++)
#pragma unroll
            for (int r = 0; r < 4; r++) sacc[nt][r] = 0.f;

#pragma unroll
        for (int ks = 0; ks < 8; ks++) {
            int kp = ks * 8 + 2 * c0;     // pair word offset within row
            uint32_t a[4];
            {
                uint2 qa0 = *(const uint2*)&Qs[(warpM + r0) * ATS + kp];
                uint2 qa1 = *(const uint2*)&Qs[(warpM + r0 + 8) * ATS + kp];
                a[0] = qa0.x; a[2] = qa0.y;
                a[1] = qa1.x; a[3] = qa1.y;
            }
#pragma unroll
            for (int nt = 0; nt < 8; nt++) {
                uint2 kb = *(const uint2*)&Ks[(nt * 8 + r0) * ATS + kp];
                uint32_t bb[2] = { kb.x, kb.y };
                mma_tf32(sacc[nt], a, bb, sacc[nt]);
            }
        }

        // ---- online softmax in log2 domain ----
        float mt0 = -1e30f, mt1 = -1e30f;
#pragma unroll
        for (int nt = 0; nt < 8; nt++) {
#pragma unroll
            for (int r = 0; r < 4; r++) sacc[nt][r] *= SCALE_LOG2E;
            mt0 = fmaxf(mt0, fmaxf(sacc[nt][0], sacc[nt][1]));
            mt1 = fmaxf(mt1, fmaxf(sacc[nt][2], sacc[nt][3]));
        }
        mt0 = fmaxf(mt0, __shfl_xor_sync(0xffffffffu, mt0, 1));
        mt0 = fmaxf(mt0, __shfl_xor_sync(0xffffffffu, mt0, 2));
        mt1 = fmaxf(mt1, __shfl_xor_sync(0xffffffffu, mt1, 1));
        mt1 = fmaxf(mt1, __shfl_xor_sync(0xffffffffu, mt1, 2));

        float mn0 = fmaxf(m0, mt0), mn1 = fmaxf(m1, mt1);
        bool upd = __any_sync(0xffffffffu, (mn0 > m0) || (mn1 > m1));
        if (upd) {
            float corr0 = ex2f(m0 - mn0), corr1 = ex2f(m1 - mn1);
            m0 = mn0; m1 = mn1;
            l0 *= corr0; l1 *= corr1;
#pragma unroll
            for (int nt = 0; nt < 8; nt++) {
                o_acc[nt][0] *= corr0; o_acc[nt][1] *= corr0;
                o_acc[nt][2] *= corr1; o_acc[nt][3] *= corr1;
            }
        }

        float rs0 = 0.f, rs1 = 0.f;
#pragma unroll
        for (int nt = 0; nt < 8; nt++) {
            float p00 = ex2f(sacc[nt][0] - m0);
            float p01 = ex2f(sacc[nt][1] - m0);
            float p10 = ex2f(sacc[nt][2] - m1);
            float p11 = ex2f(sacc[nt][3] - m1);
            rs0 += p00 + p01; rs1 += p10 + p11;
            uint2 u0 = make_uint2(f2tf32(p00), f2tf32(p01));
            uint2 u1 = make_uint2(f2tf32(p10), f2tf32(p11));
            *(uint2*)&Ps[(warpM + r0) * ATS + nt * 8 + 2 * c0] = u0;
            *(uint2*)&Ps[(warpM + r0 + 8) * ATS + nt * 8 + 2 * c0] = u1;
        }
        rs0 += __shfl_xor_sync(0xffffffffu, rs0, 1);
        rs0 += __shfl_xor_sync(0xffffffffu, rs0, 2);
        rs1 += __shfl_xor_sync(0xffffffffu, rs1, 1);
        rs1 += __shfl_xor_sync(0xffffffffu, rs1, 2);
        l0 += rs0;
        l1 += rs1;

        __syncwarp();

        // ---- O += P @ V (unchanged) ----
#pragma unroll
        for (int ks = 0; ks < 8; ks++) {
            int kk = ks * 8;
            uint32_t a[4];
            a[0] = Ps[(warpM + r0) * ATS + kk + c0];
            a[1] = Ps[(warpM + r0 + 8) * ATS + kk + c0];
            a[2] = Ps[(warpM + r0) * ATS + kk + c0 + 4];
            a[3] = Ps[(warpM + r0 + 8) * ATS + kk + c0 + 4];
#pragma unroll
            for (int nt = 0; nt < 8; nt++) {
                uint32_t bb[2];
                bb[0] = Vs[(kk + c0) * ATS + nt * 8 + r0];
                bb[1] = Vs[(kk + c0 + 4) * ATS + nt * 8 + r0];
                mma_tf32(o_acc[nt], a, bb, o_acc[nt]);
            }
        }
    }

    // epilogue: /l, round, scatter to [B, L, H*64 + d]
    float inv0 = 1.0f / l0, inv1 = 1.0f / l1;
    size_t row0 = (size_t)b * SEQ + qt * 64 + warpM + r0;
    float* O0 = out + row0 * DMODEL + h * HDIM;
    float* O1 = O0 + 8 * DMODEL;
#pragma unroll
    for (int nt = 0; nt < 8; nt++) {
        int col = nt * 8 + 2 * c0;
        float2 a = make_float2(rnd_tf32(o_acc[nt][0] * inv0),
                               rnd_tf32(o_acc[nt][1] * inv0));
        float2 c = make_float2(rnd_tf32(o_acc[nt][2] * inv1),
                               rnd_tf32(o_acc[nt][3] * inv1));
        *(float2*)(O0 + col) = a;
        *(float2*)(O1 + col) = c;
    }
}

// =====================================================================
// LayerNorm over last dim (512). Block per row, 128 threads.
// Dual write: out_f = fp32 (residual), out_r = tf32-rounded (gemm A).
// =====================================================================
__global__ void __launch_bounds__(128) ln_kernel(
    const float* __restrict__ in, const float* __restrict__ g,
    const float* __restrict__ b, float* __restrict__ out_f,
    float* __restrict__ out_r)
{
    int row = blockIdx.x;
    int tid = threadIdx.x;
    float4 v4 = *(const float4*)(in + (size_t)row * DMODEL + tid * 4);
    float s  = v4.x + v4.y + v4.z + v4.w;
    float sq = v4.x * v4.x + v4.y * v4.y + v4.z * v4.z + v4.w * v4.w;
#pragma unroll
    for (int off = 16; off > 0; off >>= 1) {
        s  += __shfl_xor_sync(0xffffffffu, s, off);
        sq += __shfl_xor_sync(0xffffffffu, sq, off);
    }
    __shared__ float ss[4], sqs[4];
    int wid = tid >> 5;
    if ((tid & 31) == 0) { ss[wid] = s; sqs[wid] = sq; }
    __syncthreads();
    s  = ss[0] + ss[1] + ss[2] + ss[3];
    sq = sqs[0] + sqs[1] + sqs[2] + sqs[3];
    float mu  = s * (1.0f / DMODEL);
    float var = sq * (1.0f / DMODEL) - mu * mu;
    float inv = rsqrtf(var + 1e-5f);
    float4 gv = *(const float4*)(g + tid * 4);
    float4 bv = *(const float4*)(b + tid * 4);
    float4 o;
    o.x = (v4.x - mu) * inv * gv.x + bv.x;
    o.y = (v4.y - mu) * inv * gv.y + bv.y;
    o.z = (v4.z - mu) * inv * gv.z + bv.z;
    o.w = (v4.w - mu) * inv * gv.w + bv.w;
    *(float4*)(out_f + (size_t)row * DMODEL + tid * 4) = o;
    if (out_r)
        *(uint4*)(out_r + (size_t)row * DMODEL + tid * 4) = cvt4(o);
}

// =====================================================================
// host launcher
// =====================================================================
extern "C" void kernel_launch(void* const* d_in, const int* in_sizes, int n_in,
                              void* d_out, int out_size)
{
    const int*   src  = (const int*)  d_in[0];
    const float* emb  = (const float*)d_in[1];
    const float* pe   = (const float*)d_in[2];
    const float* Wq   = (const float*)d_in[3];
    const float* bq   = (const float*)d_in[4];
    const float* Wk   = (const float*)d_in[5];
    const float* bk   = (const float*)d_in[6];
    const float* Wv   = (const float*)d_in[7];
    const float* bv   = (const float*)d_in[8];
    const float* Wo   = (const float*)d_in[9];
    const float* bo   = (const float*)d_in[10];
    const float* W1   = (const float*)d_in[11];
    const float* b1   = (const float*)d_in[12];
    const float* W2   = (const float*)d_in[13];
    const float* b2   = (const float*)d_in[14];
    const float* g1   = (const float*)d_in[15];
    const float* be1  = (const float*)d_in[16];
    const float* g2   = (const float*)d_in[17];
    const float* be2  = (const float*)d_in[18];
    float* outp = (float*)d_out;

    float *x, *xr, *q, *k, *v, *attn, *tmp, *ff, *wr;
    cudaGetSymbolAddress((void**)&x,    g_x);
    cudaGetSymbolAddress((void**)&xr,   g_xr);
    cudaGetSymbolAddress((void**)&q,    g_q);
    cudaGetSymbolAddress((void**)&k,    g_k);
    cudaGetSymbolAddress((void**)&v,    g_v);
    cudaGetSymbolAddress((void**)&attn, g_attn);
    cudaGetSymbolAddress((void**)&tmp,  g_tmp);
    cudaGetSymbolAddress((void**)&ff,   g_ff);
    cudaGetSymbolAddress((void**)&wr,   g_wr);

    cudaFuncSetAttribute(attn_mma,
                         cudaFuncAttributeMaxDynamicSharedMemorySize, ATTN3_SMEM);
    cudaFuncSetAttribute(gemm_mma,
                         cudaFuncAttributeMaxDynamicSharedMemorySize, GS3_SMEM);
    cudaFuncSetAttribute(gemm_qkv,
                         cudaFuncAttributeMaxDynamicSharedMemorySize, GS3_SMEM);

    // permuted weight segments (17/16 padded)
    const size_t DDP = 278528;            // per-layer dxd tile bytes/4
    const size_t DFP = 1114112;           // per-layer dxff
    float* WqR = wr;
    float* WkR = wr + 1671168;
    float* WvR = wr + 3342336;
    float* WoR = wr + 5013504;
    float* W1R = wr + 6684672;
    float* W2R = wr + 13369344;

    round_all_kernel<<<dim3(256, NLAYERS, 6), 256>>>(Wq, Wk, Wv, Wo, W1, W2, wr);

    embed_kernel<<<MROWS, 128>>>(src, emb, pe, x, xr);

    dim3 gQKV(DMODEL / 128, MROWS / 128, 3);
    dim3 gProj(DMODEL / 128, MROWS / 128);
    dim3 gFF1(DFF / 128,    MROWS / 128);
    dim3 gAttn(SEQ / 64, BATCH * NHEADS);    // (32, 32)

    for (int L = 0; L < NLAYERS; L++) {
        const size_t vd  = (size_t)L * DMODEL;
        const size_t vf  = (size_t)L * DFF;
        const size_t pdd = (size_t)L * DDP;
        const size_t pdf = (size_t)L * DFP;

        gemm_qkv<<<gQKV, 256, GS3_SMEM>>>(xr, WqR + pdd, WkR + pdd, WvR + pdd,
                                          bq + vd, bk + vd, bv + vd, q, k, v);

        attn_mma<<<gAttn, 128, ATTN3_SMEM>>>(q, k, v, attn);

        gemm_mma<<<gProj, 256, GS3_SMEM>>>(attn, WoR + pdd, bo + vd, x, tmp,
                                           MROWS, DMODEL, DMODEL, 0, 0);
        ln_kernel<<<MROWS, 128>>>(tmp, g1 + vd, be1 + vd, x, xr);

        gemm_mma<<<gFF1, 256, GS3_SMEM>>>(xr, W1R + pdf, b1 + vf, nullptr, ff,
                                          MROWS, DFF, DMODEL, 1, 1);
        gemm_mma<<<gProj, 256, GS3_SMEM>>>(ff, W2R + pdf, b2 + vd, x, tmp,
                                           MROWS, DMODEL, DFF, 0, 0);
        ln_kernel<<<MROWS, 128>>>(tmp, g2 + vd, be2 + vd,
                                  (L == NLAYERS - 1) ? outp : x,
                                  (L == NLAYERS - 1) ? nullptr : xr);
    }
}

// round 13
// speedup vs baseline: 1.0800x; 1.0800x over previous
#include <cuda_runtime.h>
#include <cuda_bf16.h>
#include <cstdint>
#include <cstddef>

// Problem constants
#define BATCH   4
#define SEQ     2048
#define DMODEL  512
#define NHEADS  8
#define HDIM    64
#define DFF     2048
#define NLAYERS 6
#define MROWS   (BATCH * SEQ)            // 8192

// -------- scratch (device globals; no allocation allowed) --------
__device__ float g_x   [MROWS * DMODEL];   // fp32 residual stream
__device__ float g_xr  [MROWS * DMODEL];   // tf32-rounded copy (gemm A input)
__device__ float g_q   [MROWS * DMODEL];
__device__ float g_k   [MROWS * DMODEL];
__device__ float g_v   [MROWS * DMODEL];
__device__ float g_attn[MROWS * DMODEL];
__device__ float g_tmp [MROWS * DMODEL];
__device__ float g_ff  [MROWS * DFF];
// tf32-rounded weights
#define WR_TOTAL 18874368
__device__ float g_wr  [WR_TOTAL];

// ==================== helpers ====================
__device__ __forceinline__ uint32_t f2tf32(float x) {
    uint32_t u;
    asm("cvt.rna.tf32.f32 %0, %1;" : "=r"(u) : "f"(x));
    return u;
}
__device__ __forceinline__ float rnd_tf32(float x) {
    return __uint_as_float(f2tf32(x));
}
__device__ __forceinline__ uint4 cvt4(float4 v) {
    return make_uint4(f2tf32(v.x), f2tf32(v.y), f2tf32(v.z), f2tf32(v.w));
}
__device__ __forceinline__ uint32_t smem_u32(const void* p) {
    uint32_t a;
    asm("{ .reg .u64 t; cvta.to.shared.u64 t, %1; cvt.u32.u64 %0, t; }"
        : "=r"(a) : "l"(p));
    return a;
}
__device__ __forceinline__ void cp16(uint32_t dst, const void* src) {
    asm volatile("cp.async.cg.shared.global [%0], [%1], 16;"
                 :: "r"(dst), "l"(src));
}
#define CP_COMMIT() asm volatile("cp.async.commit_group;" ::: "memory")
#define CP_WAIT0()  asm volatile("cp.async.wait_group 0;" ::: "memory")
#define CP_WAIT1()  asm volatile("cp.async.wait_group 1;" ::: "memory")

// mma.sync m16n8k8 tf32: d = a*b + c  (f32 accum)
__device__ __forceinline__ void mma_tf32(
    float* d, const uint32_t* a, const uint32_t* b, const float* c)
{
    asm volatile(
        "mma.sync.aligned.m16n8k8.row.col.f32.tf32.tf32.f32 "
        "{%0,%1,%2,%3}, {%4,%5,%6,%7}, {%8,%9}, {%10,%11,%12,%13};"
        : "=f"(d[0]), "=f"(d[1]), "=f"(d[2]), "=f"(d[3])
        : "r"(a[0]), "r"(a[1]), "r"(a[2]), "r"(a[3]),
          "r"(b[0]), "r"(b[1]),
          "f"(c[0]), "f"(c[1]), "f"(c[2]), "f"(c[3]));
}

// =====================================================================
// Weight rounding passes (z-indexed, 2 launches total)
// =====================================================================
__global__ void __launch_bounds__(256) round4_kernel(
    const float* __restrict__ s0, const float* __restrict__ s1,
    const float* __restrict__ s2, const float* __restrict__ s3,
    float* __restrict__ d0, float* __restrict__ d1,
    float* __restrict__ d2, float* __restrict__ d3)
{
    const float* s; float* d;
    if (blockIdx.z == 0)      { s = s0; d = d0; }
    else if (blockIdx.z == 1) { s = s1; d = d1; }
    else if (blockIdx.z == 2) { s = s2; d = d2; }
    else                      { s = s3; d = d3; }
    int i = blockIdx.x * blockDim.x + threadIdx.x;
    float4 v = *(const float4*)(s + (size_t)i * 4);
    *(uint4*)(d + (size_t)i * 4) = cvt4(v);
}

__global__ void __launch_bounds__(256) round2_kernel(
    const float* __restrict__ s0, const float* __restrict__ s1,
    float* __restrict__ d0, float* __restrict__ d1)
{
    const float* s; float* d;
    if (blockIdx.z == 0) { s = s0; d = d0; }
    else                 { s = s1; d = d1; }
    int i = blockIdx.x * blockDim.x + threadIdx.x;
    float4 v = *(const float4*)(s + (size_t)i * 4);
    *(uint4*)(d + (size_t)i * 4) = cvt4(v);
}

// =====================================================================
// Embedding + positional encoding: dual write (fp32 + rounded)
// =====================================================================
__global__ void __launch_bounds__(128) embed_kernel(
    const int* __restrict__ src, const float* __restrict__ emb,
    const float* __restrict__ pe, float* __restrict__ xf,
    float* __restrict__ xr)
{
    int bl  = blockIdx.x;
    int l   = bl & (SEQ - 1);
    int tok = src[bl];
    int c   = threadIdx.x * 4;
    float4 e = *(const float4*)(emb + (size_t)tok * DMODEL + c);
    float4 p = *(const float4*)(pe  + (size_t)l   * DMODEL + c);
    float4 o; o.x = e.x + p.x; o.y = e.y + p.y; o.z = e.z + p.z; o.w = e.w + p.w;
    *(float4*)(xf + (size_t)bl * DMODEL + c) = o;
    *(uint4*)(xr + (size_t)bl * DMODEL + c) = cvt4(o);
}

// =====================================================================
// Tensor-core GEMM v3 (tf32 mma.sync): C = A@W + bias (+res)(+relu)(+rnd)
// Both operands pre-rounded tf32 in gmem -> pure cp.async pipeline.
// CTA 128x128, 8 warps (2x4, warp tile 64x32), KC=32, 3-stage pipeline.
// =====================================================================
#define KC3    32
#define AW     36
#define BW     136
#define A_STG  (128 * AW)
#define B_STG  (KC3 * BW)
#define STG_W  (A_STG + B_STG)
#define GS3_SMEM (3 * STG_W * 4)          // 107520 bytes

__device__ __forceinline__ void gemm_body(
    const float* __restrict__ A, const float* __restrict__ Wr,
    const float* __restrict__ bias, const float* __restrict__ res,
    float* __restrict__ C, int M, int N, int K, int relu, int rnd,
    int bxx, int byy)
{
    extern __shared__ uint32_t sm[];
    uint32_t sbase = smem_u32(sm);

    int tid  = threadIdx.x;
    int lane = tid & 31;
    int wid  = tid >> 5;
    int bm = byy << 7, bn = bxx << 7;
    int warpM = (wid >> 2) * 64;
    int warpN = (wid & 3) * 32;
    int r0 = lane >> 2, c0 = lane & 3;

    int aRow[4], aC16[4], bKr[4], bC16[4];
#pragma unroll
    for (int i = 0; i < 4; i++) {
        int id = tid + i * 256;
        aRow[i] = id >> 3;  aC16[i] = id & 7;
        bKr[i]  = id >> 5;  bC16[i] = id & 31;
    }

    float acc[4][4][4];
#pragma unroll
    for (int mt = 0; mt < 4; mt++)
#pragma unroll
        for (int nt = 0; nt < 4; nt++)
#pragma unroll
            for (int r = 0; r < 4; r++) acc[mt][nt][r] = 0.f;

    int nst = K / KC3;

    auto issue_stage = [&](int st, int kc) {
        uint32_t aB = sbase + (st * STG_W) * 4;
        uint32_t bBq = sbase + (st * STG_W + A_STG) * 4;
#pragma unroll
        for (int i = 0; i < 4; i++)
            cp16(aB + (aRow[i] * AW + aC16[i] * 4) * 4,
                 A + (size_t)(bm + aRow[i]) * K + kc + aC16[i] * 4);
#pragma unroll
        for (int i = 0; i < 4; i++)
            cp16(bBq + (bKr[i] * BW + bC16[i] * 4) * 4,
                 Wr + (size_t)(kc + bKr[i]) * N + bn + bC16[i] * 4);
        CP_COMMIT();
    };

    issue_stage(0, 0);
    issue_stage(1, KC3);

    for (int s = 0; s < nst; s++) {
        int cur = s % 3;
        if (s + 1 < nst) CP_WAIT1(); else CP_WAIT0();
        __syncthreads();
        if (s + 2 < nst) issue_stage((s + 2) % 3, (s + 2) * KC3);

        const uint32_t* Ab = sm + cur * STG_W;
        const uint32_t* Bb = Ab + A_STG;
#pragma unroll
        for (int ks = 0; ks < 4; ks++) {
            int k0 = ks * 8 + c0;
            uint32_t af[4][4], bf[4][2];
#pragma unroll
            for (int mt = 0; mt < 4; mt++) {
                int m0 = warpM + mt * 16 + r0;
                af[mt][0] = Ab[m0 * AW + k0];
                af[mt][1] = Ab[(m0 + 8) * AW + k0];
                af[mt][2] = Ab[m0 * AW + k0 + 4];
                af[mt][3] = Ab[(m0 + 8) * AW + k0 + 4];
            }
#pragma unroll
            for (int nt = 0; nt < 4; nt++) {
                int n0 = warpN + nt * 8 + r0;
                bf[nt][0] = Bb[k0 * BW + n0];
                bf[nt][1] = Bb[(k0 + 4) * BW + n0];
            }
#pragma unroll
            for (int mt = 0; mt < 4; mt++)
#pragma unroll
                for (int nt = 0; nt < 4; nt++)
                    mma_tf32(acc[mt][nt], af[mt], bf[nt], acc[mt][nt]);
        }
        __syncthreads();
    }

#pragma unroll
    for (int mt = 0; mt < 4; mt++) {
        int row0 = bm + warpM + mt * 16 + r0;
#pragma unroll
        for (int h = 0; h < 2; h++) {
            int row = row0 + h * 8;
            float* crow = C + (size_t)row * N;
            const float* rrow = res ? (res + (size_t)row * N) : nullptr;
#pragma unroll
            for (int nt = 0; nt < 4; nt++) {
                int col = bn + warpN + nt * 8 + 2 * c0;
                float2 b2 = *(const float2*)(bias + col);
                float2 o;
                o.x = acc[mt][nt][h * 2 + 0] + b2.x;
                o.y = acc[mt][nt][h * 2 + 1] + b2.y;
                if (rrow) {
                    float2 r2 = *(const float2*)(rrow + col);
                    o.x += r2.x; o.y += r2.y;
                }
                if (relu) { o.x = fmaxf(o.x, 0.f); o.y = fmaxf(o.y, 0.f); }
                if (rnd)  { o.x = rnd_tf32(o.x);   o.y = rnd_tf32(o.y); }
                *(float2*)(crow + col) = o;
            }
        }
    }
}

__global__ void __launch_bounds__(256, 2) gemm_mma(
    const float* __restrict__ A, const float* __restrict__ Wr,
    const float* __restrict__ bias, const float* __restrict__ res,
    float* __restrict__ C, int M, int N, int K, int relu, int rnd)
{
    gemm_body(A, Wr, bias, res, C, M, N, K, relu, rnd,
              blockIdx.x, blockIdx.y);
}

__global__ void __launch_bounds__(256, 2) gemm_qkv(
    const float* __restrict__ x,
    const float* __restrict__ Wq, const float* __restrict__ Wk,
    const float* __restrict__ Wv,
    const float* __restrict__ bq, const float* __restrict__ bk,
    const float* __restrict__ bv,
    float* __restrict__ q, float* __restrict__ k, float* __restrict__ v)
{
    const float* W; const float* bias; float* C;
    if (blockIdx.z == 0)      { W = Wq; bias = bq; C = q; }
    else if (blockIdx.z == 1) { W = Wk; bias = bk; C = k; }
    else                      { W = Wv; bias = bv; C = v; }
    gemm_body(x, W, bias, nullptr, C, MROWS, DMODEL, DMODEL, 0, 1,
              blockIdx.x, blockIdx.y);
}

// =====================================================================
// Tensor-core flash attention (tf32 mma.sync) — round-9 structure
// (64x64 tiles, 128 thr, stride 68, dbuf K/V, cp.async) with Q
// fragments hoisted into registers (loaded once, reused all 32 iters).
// smem: Q | P | K0 | V0 | K1 | V1, each 64x68 words.
// =====================================================================
#define ATS 68
#define TILE_W (64 * ATS)                 // 4352 words
#define ATTN3_SMEM (6 * TILE_W * 4)       // 104448 bytes

__device__ __forceinline__ void cp_tile(
    uint32_t dstbase, const float* __restrict__ g, int tid)
{
#pragma unroll
    for (int i = 0; i < 8; i++) {
        int id  = tid + i * 128;
        int row = id >> 4, c16 = id & 15;
        cp16(dstbase + (row * ATS + c16 * 4) * 4, g + row * 64 + c16 * 4);
    }
}

__global__ void __launch_bounds__(128, 2) attn_mma(
    const float* __restrict__ q, const float* __restrict__ k,
    const float* __restrict__ v, float* __restrict__ out)
{
    extern __shared__ uint32_t smu[];
    uint32_t sbase = smem_u32(smu);
    uint32_t* Qs = smu;
    uint32_t* Ps = smu + TILE_W;

    int tid  = threadIdx.x;
    int lane = tid & 31;
    int wid  = tid >> 5;
    int bh   = blockIdx.y;
    int qt   = blockIdx.x;
    int b    = bh >> 3, h = bh & 7;

    const float* Qg = q + ((size_t)bh * SEQ + qt * 64) * HDIM;
    const float* Kg = k + (size_t)bh * SEQ * HDIM;
    const float* Vg = v + (size_t)bh * SEQ * HDIM;

    // prolog: Q + K0 + V0 in one group
    cp_tile(sbase, Qg, tid);
    cp_tile(sbase + (2 * TILE_W) * 4, Kg, tid);
    cp_tile(sbase + (3 * TILE_W) * 4, Vg, tid);
    CP_COMMIT();

    int warpM = wid * 16;
    int r0 = lane >> 2, c0 = lane & 3;

    // wait prolog, then hoist Q fragments into registers (once)
    CP_WAIT0();
    __syncthreads();
    uint32_t qf[8][4];
#pragma unroll
    for (int ks = 0; ks < 8; ks++) {
        int kk = ks * 8 + c0;
        qf[ks][0] = Qs[(warpM + r0) * ATS + kk];
        qf[ks][1] = Qs[(warpM + r0 + 8) * ATS + kk];
        qf[ks][2] = Qs[(warpM + r0) * ATS + kk + 4];
        qf[ks][3] = Qs[(warpM + r0 + 8) * ATS + kk + 4];
    }

    float m0 = -1e30f, m1 = -1e30f, l0 = 0.f, l1 = 0.f;
    float o_acc[8][4];
#pragma unroll
    for (int nt = 0; nt < 8; nt++)
#pragma unroll
        for (int r = 0; r < 4; r++) o_acc[nt][r] = 0.f;

    for (int kt = 0; kt < SEQ / 64; kt++) {
        int cur = kt & 1, nb = cur ^ 1;
        if (kt > 0) {
            CP_WAIT0();
            __syncthreads();
        }
        if (kt + 1 < SEQ / 64) {
            cp_tile(sbase + ((2 + 2 * nb) * TILE_W) * 4,
                    Kg + (size_t)(kt + 1) * 64 * HDIM, tid);
            cp_tile(sbase + ((3 + 2 * nb) * TILE_W) * 4,
                    Vg + (size_t)(kt + 1) * 64 * HDIM, tid);
            CP_COMMIT();
        }
        const uint32_t* Ks = smu + (2 + 2 * cur) * TILE_W;
        const uint32_t* Vs = smu + (3 + 2 * cur) * TILE_W;

        // ---- S = Q K^T (Q from registers) ----
        float sacc[8][4];
#pragma unroll
        for (int nt = 0; nt < 8; nt++)
#pragma unroll
            for (int r = 0; r < 4; r++) sacc[nt][r] = 0.f;

#pragma unroll
        for (int ks = 0; ks < 8; ks++) {
            int kk = ks * 8 + c0;
#pragma unroll
            for (int nt = 0; nt < 8; nt++) {
                uint32_t bb[2];
                bb[0] = Ks[(nt * 8 + r0) * ATS + kk];
                bb[1] = Ks[(nt * 8 + r0) * ATS + kk + 4];
                mma_tf32(sacc[nt], qf[ks], bb, sacc[nt]);
            }
        }

        // ---- online softmax ----
        float mt0 = -1e30f, mt1 = -1e30f;
#pragma unroll
        for (int nt = 0; nt < 8; nt++) {
#pragma unroll
            for (int r = 0; r < 4; r++) sacc[nt][r] *= 0.125f;
            mt0 = fmaxf(mt0, fmaxf(sacc[nt][0], sacc[nt][1]));
            mt1 = fmaxf(mt1, fmaxf(sacc[nt][2], sacc[nt][3]));
        }
        mt0 = fmaxf(mt0, __shfl_xor_sync(0xffffffffu, mt0, 1));
        mt0 = fmaxf(mt0, __shfl_xor_sync(0xffffffffu, mt0, 2));
        mt1 = fmaxf(mt1, __shfl_xor_sync(0xffffffffu, mt1, 1));
        mt1 = fmaxf(mt1, __shfl_xor_sync(0xffffffffu, mt1, 2));

        float mn0 = fmaxf(m0, mt0), mn1 = fmaxf(m1, mt1);
        float corr0 = __expf(m0 - mn0), corr1 = __expf(m1 - mn1);
        m0 = mn0; m1 = mn1;

        float rs0 = 0.f, rs1 = 0.f;
#pragma unroll
        for (int nt = 0; nt < 8; nt++) {
            float p00 = __expf(sacc[nt][0] - mn0);
            float p01 = __expf(sacc[nt][1] - mn0);
            float p10 = __expf(sacc[nt][2] - mn1);
            float p11 = __expf(sacc[nt][3] - mn1);
            rs0 += p00 + p01; rs1 += p10 + p11;
            uint2 u0 = make_uint2(f2tf32(p00), f2tf32(p01));
            uint2 u1 = make_uint2(f2tf32(p10), f2tf32(p11));
            *(uint2*)&Ps[(warpM + r0) * ATS + nt * 8 + 2 * c0] = u0;
            *(uint2*)&Ps[(warpM + r0 + 8) * ATS + nt * 8 + 2 * c0] = u1;
        }
        rs0 += __shfl_xor_sync(0xffffffffu, rs0, 1);
        rs0 += __shfl_xor_sync(0xffffffffu, rs0, 2);
        rs1 += __shfl_xor_sync(0xffffffffu, rs1, 1);
        rs1 += __shfl_xor_sync(0xffffffffu, rs1, 2);
        l0 = l0 * corr0 + rs0;
        l1 = l1 * corr1 + rs1;

#pragma unroll
        for (int nt = 0; nt < 8; nt++) {
            o_acc[nt][0] *= corr0; o_acc[nt][1] *= corr0;
            o_acc[nt][2] *= corr1; o_acc[nt][3] *= corr1;
        }
        __syncwarp();

        // ---- O += P @ V ----
#pragma unroll
        for (int ks = 0; ks < 8; ks++) {
            int kk = ks * 8;
            uint32_t a[4];
            a[0] = Ps[(warpM + r0) * ATS + kk + c0];
            a[1] = Ps[(warpM + r0 + 8) * ATS + kk + c0];
            a[2] = Ps[(warpM + r0) * ATS + kk + c0 + 4];
            a[3] = Ps[(warpM + r0 + 8) * ATS + kk + c0 + 4];
#pragma unroll
            for (int nt = 0; nt < 8; nt++) {
                uint32_t bb[2];
                bb[0] = Vs[(kk + c0) * ATS + nt * 8 + r0];
                bb[1] = Vs[(kk + c0 + 4) * ATS + nt * 8 + r0];
                mma_tf32(o_acc[nt], a, bb, o_acc[nt]);
            }
        }
    }

    // epilogue: /l, round, scatter to [B, L, H*64 + d]
    float inv0 = 1.0f / l0, inv1 = 1.0f / l1;
    size_t row0 = (size_t)b * SEQ + qt * 64 + warpM + r0;
    float* O0 = out + row0 * DMODEL + h * HDIM;
    float* O1 = O0 + 8 * DMODEL;
#pragma unroll
    for (int nt = 0; nt < 8; nt++) {
        int col = nt * 8 + 2 * c0;
        float2 a = make_float2(rnd_tf32(o_acc[nt][0] * inv0),
                               rnd_tf32(o_acc[nt][1] * inv0));
        float2 c = make_float2(rnd_tf32(o_acc[nt][2] * inv1),
                               rnd_tf32(o_acc[nt][3] * inv1));
        *(float2*)(O0 + col) = a;
        *(float2*)(O1 + col) = c;
    }
}

// =====================================================================
// LayerNorm over last dim (512). Block per row, 128 threads.
// Dual write: out_f = fp32 (residual), out_r = tf32-rounded (gemm A).
// =====================================================================
__global__ void __launch_bounds__(128) ln_kernel(
    const float* __restrict__ in, const float* __restrict__ g,
    const float* __restrict__ b, float* __restrict__ out_f,
    float* __restrict__ out_r)
{
    int row = blockIdx.x;
    int tid = threadIdx.x;
    float4 v4 = *(const float4*)(in + (size_t)row * DMODEL + tid * 4);
    float s  = v4.x + v4.y + v4.z + v4.w;
    float sq = v4.x * v4.x + v4.y * v4.y + v4.z * v4.z + v4.w * v4.w;
#pragma unroll
    for (int off = 16; off > 0; off >>= 1) {
        s  += __shfl_xor_sync(0xffffffffu, s, off);
        sq += __shfl_xor_sync(0xffffffffu, sq, off);
    }
    __shared__ float ss[4], sqs[4];
    int wid = tid >> 5;
    if ((tid & 31) == 0) { ss[wid] = s; sqs[wid] = sq; }
    __syncthreads();
    s  = ss[0] + ss[1] + ss[2] + ss[3];
    sq = sqs[0] + sqs[1] + sqs[2] + sqs[3];
    float mu  = s * (1.0f / DMODEL);
    float var = sq * (1.0f / DMODEL) - mu * mu;
    float inv = rsqrtf(var + 1e-5f);
    float4 gv = *(const float4*)(g + tid * 4);
    float4 bv = *(const float4*)(b + tid * 4);
    float4 o;
    o.x = (v4.x - mu) * inv * gv.x + bv.x;
    o.y = (v4.y - mu) * inv * gv.y + bv.y;
    o.z = (v4.z - mu) * inv * gv.z + bv.z;
    o.w = (v4.w - mu) * inv * gv.w + bv.w;
    *(float4*)(out_f + (size_t)row * DMODEL + tid * 4) = o;
    if (out_r)
        *(uint4*)(out_r + (size_t)row * DMODEL + tid * 4) = cvt4(o);
}

// =====================================================================
// host launcher
// =====================================================================
extern "C" void kernel_launch(void* const* d_in, const int* in_sizes, int n_in,
                              void* d_out, int out_size)
{
    const int*   src  = (const int*)  d_in[0];
    const float* emb  = (const float*)d_in[1];
    const float* pe   = (const float*)d_in[2];
    const float* Wq   = (const float*)d_in[3];
    const float* bq   = (const float*)d_in[4];
    const float* Wk   = (const float*)d_in[5];
    const float* bk   = (const float*)d_in[6];
    const float* Wv   = (const float*)d_in[7];
    const float* bv   = (const float*)d_in[8];
    const float* Wo   = (const float*)d_in[9];
    const float* bo   = (const float*)d_in[10];
    const float* W1   = (const float*)d_in[11];
    const float* b1   = (const float*)d_in[12];
    const float* W2   = (const float*)d_in[13];
    const float* b2   = (const float*)d_in[14];
    const float* g1   = (const float*)d_in[15];
    const float* be1  = (const float*)d_in[16];
    const float* g2   = (const float*)d_in[17];
    const float* be2  = (const float*)d_in[18];
    float* outp = (float*)d_out;

    float *x, *xr, *q, *k, *v, *attn, *tmp, *ff, *wr;
    cudaGetSymbolAddress((void**)&x,    g_x);
    cudaGetSymbolAddress((void**)&xr,   g_xr);
    cudaGetSymbolAddress((void**)&q,    g_q);
    cudaGetSymbolAddress((void**)&k,    g_k);
    cudaGetSymbolAddress((void**)&v,    g_v);
    cudaGetSymbolAddress((void**)&attn, g_attn);
    cudaGetSymbolAddress((void**)&tmp,  g_tmp);
    cudaGetSymbolAddress((void**)&ff,   g_ff);
    cudaGetSymbolAddress((void**)&wr,   g_wr);

    cudaFuncSetAttribute(attn_mma,
                         cudaFuncAttributeMaxDynamicSharedMemorySize, ATTN3_SMEM);
    cudaFuncSetAttribute(gemm_mma,
                         cudaFuncAttributeMaxDynamicSharedMemorySize, GS3_SMEM);
    cudaFuncSetAttribute(gemm_qkv,
                         cudaFuncAttributeMaxDynamicSharedMemorySize, GS3_SMEM);

    const size_t DD6 = (size_t)NLAYERS * DMODEL * DMODEL;
    const size_t DF6 = (size_t)NLAYERS * DMODEL * DFF;
    float* WqR = wr;
    float* WkR = WqR + DD6;
    float* WvR = WkR + DD6;
    float* WoR = WvR + DD6;
    float* W1R = WoR + DD6;
    float* W2R = W1R + DF6;

    round4_kernel<<<dim3((unsigned)(DD6 / 4 / 256), 1, 4), 256>>>(
        Wq, Wk, Wv, Wo, WqR, WkR, WvR, WoR);
    round2_kernel<<<dim3((unsigned)(DF6 / 4 / 256), 1, 2), 256>>>(
        W1, W2, W1R, W2R);

    embed_kernel<<<MROWS, 128>>>(src, emb, pe, x, xr);

    dim3 gQKV(DMODEL / 128, MROWS / 128, 3);
    dim3 gProj(DMODEL / 128, MROWS / 128);
    dim3 gFF1(DFF / 128,    MROWS / 128);
    dim3 gAttn(SEQ / 64, BATCH * NHEADS);    // (32, 32)

    for (int L = 0; L < NLAYERS; L++) {
        const size_t vd  = (size_t)L * DMODEL;
        const size_t vf  = (size_t)L * DFF;
        const size_t wdd = (size_t)L * DMODEL * DMODEL;
        const size_t wdf = (size_t)L * DMODEL * DFF;

        gemm_qkv<<<gQKV, 256, GS3_SMEM>>>(xr, WqR + wdd, WkR + wdd, WvR + wdd,
                                          bq + vd, bk + vd, bv + vd, q, k, v);

        attn_mma<<<gAttn, 128, ATTN3_SMEM>>>(q, k, v, attn);

        gemm_mma<<<gProj, 256, GS3_SMEM>>>(attn, WoR + wdd, bo + vd, x, tmp,
                                           MROWS, DMODEL, DMODEL, 0, 0);
        ln_kernel<<<MROWS, 128>>>(tmp, g1 + vd, be1 + vd, x, xr);

        gemm_mma<<<gFF1, 256, GS3_SMEM>>>(xr, W1R + wdf, b1 + vf, nullptr, ff,
                                          MROWS, DFF, DMODEL, 1, 1);
        gemm_mma<<<gProj, 256, GS3_SMEM>>>(ff, W2R + wdf, b2 + vd, x, tmp,
                                           MROWS, DMODEL, DFF, 0, 0);
        ln_kernel<<<MROWS, 128>>>(tmp, g2 + vd, be2 + vd,
                                  (L == NLAYERS - 1) ? outp : x,
                                  (L == NLAYERS - 1) ? nullptr : xr);
    }
}

// round 14
// speedup vs baseline: 1.2236x; 1.1330x over previous
#include <cuda_runtime.h>
#include <cuda_bf16.h>
#include <cstdint>
#include <cstddef>

// Problem constants
#define BATCH   4
#define SEQ     2048
#define DMODEL  512
#define NHEADS  8
#define HDIM    64
#define DFF     2048
#define NLAYERS 6
#define MROWS   (BATCH * SEQ)            // 8192

// -------- scratch (device globals; no allocation allowed) --------
__device__ float g_x   [MROWS * DMODEL];   // fp32 residual stream
__device__ float g_xr  [MROWS * DMODEL];   // tf32-rounded copy (gemm A input)
__device__ float g_q   [MROWS * DMODEL];
__device__ float g_k   [MROWS * DMODEL];
__device__ float g_v   [MROWS * DMODEL];
__device__ float g_attn[MROWS * DMODEL];
__device__ float g_tmp [MROWS * DMODEL];
__device__ float g_ff  [MROWS * DFF];
// tf32-rounded weights
#define WR_TOTAL 18874368
__device__ float g_wr  [WR_TOTAL];

// ==================== helpers ====================
__device__ __forceinline__ uint32_t f2tf32(float x) {
    uint32_t u;
    asm("cvt.rna.tf32.f32 %0, %1;" : "=r"(u) : "f"(x));
    return u;
}
__device__ __forceinline__ float rnd_tf32(float x) {
    return __uint_as_float(f2tf32(x));
}
__device__ __forceinline__ uint4 cvt4(float4 v) {
    return make_uint4(f2tf32(v.x), f2tf32(v.y), f2tf32(v.z), f2tf32(v.w));
}
__device__ __forceinline__ uint32_t smem_u32(const void* p) {
    uint32_t a;
    asm("{ .reg .u64 t; cvta.to.shared.u64 t, %1; cvt.u32.u64 %0, t; }"
        : "=r"(a) : "l"(p));
    return a;
}
__device__ __forceinline__ void cp16(uint32_t dst, const void* src) {
    asm volatile("cp.async.cg.shared.global [%0], [%1], 16;"
                 :: "r"(dst), "l"(src));
}
#define CP_COMMIT() asm volatile("cp.async.commit_group;" ::: "memory")
#define CP_WAIT0()  asm volatile("cp.async.wait_group 0;" ::: "memory")
#define CP_WAIT1()  asm volatile("cp.async.wait_group 1;" ::: "memory")

// mma.sync m16n8k8 tf32: d = a*b + c  (f32 accum)
__device__ __forceinline__ void mma_tf32(
    float* d, const uint32_t* a, const uint32_t* b, const float* c)
{
    asm volatile(
        "mma.sync.aligned.m16n8k8.row.col.f32.tf32.tf32.f32 "
        "{%0,%1,%2,%3}, {%4,%5,%6,%7}, {%8,%9}, {%10,%11,%12,%13};"
        : "=f"(d[0]), "=f"(d[1]), "=f"(d[2]), "=f"(d[3])
        : "r"(a[0]), "r"(a[1]), "r"(a[2]), "r"(a[3]),
          "r"(b[0]), "r"(b[1]),
          "f"(c[0]), "f"(c[1]), "f"(c[2]), "f"(c[3]));
}

// =====================================================================
// Weight rounding passes (z-indexed, 2 launches total)
// =====================================================================
__global__ void __launch_bounds__(256) round4_kernel(
    const float* __restrict__ s0, const float* __restrict__ s1,
    const float* __restrict__ s2, const float* __restrict__ s3,
    float* __restrict__ d0, float* __restrict__ d1,
    float* __restrict__ d2, float* __restrict__ d3)
{
    const float* s; float* d;
    if (blockIdx.z == 0)      { s = s0; d = d0; }
    else if (blockIdx.z == 1) { s = s1; d = d1; }
    else if (blockIdx.z == 2) { s = s2; d = d2; }
    else                      { s = s3; d = d3; }
    int i = blockIdx.x * blockDim.x + threadIdx.x;
    float4 v = *(const float4*)(s + (size_t)i * 4);
    *(uint4*)(d + (size_t)i * 4) = cvt4(v);
}

__global__ void __launch_bounds__(256) round2_kernel(
    const float* __restrict__ s0, const float* __restrict__ s1,
    float* __restrict__ d0, float* __restrict__ d1)
{
    const float* s; float* d;
    if (blockIdx.z == 0) { s = s0; d = d0; }
    else                 { s = s1; d = d1; }
    int i = blockIdx.x * blockDim.x + threadIdx.x;
    float4 v = *(const float4*)(s + (size_t)i * 4);
    *(uint4*)(d + (size_t)i * 4) = cvt4(v);
}

// =====================================================================
// Embedding + positional encoding: dual write (fp32 + rounded)
// =====================================================================
__global__ void __launch_bounds__(128) embed_kernel(
    const int* __restrict__ src, const float* __restrict__ emb,
    const float* __restrict__ pe, float* __restrict__ xf,
    float* __restrict__ xr)
{
    int bl  = blockIdx.x;
    int l   = bl & (SEQ - 1);
    int tok = src[bl];
    int c   = threadIdx.x * 4;
    float4 e = *(const float4*)(emb + (size_t)tok * DMODEL + c);
    float4 p = *(const float4*)(pe  + (size_t)l   * DMODEL + c);
    float4 o; o.x = e.x + p.x; o.y = e.y + p.y; o.z = e.z + p.z; o.w = e.w + p.w;
    *(float4*)(xf + (size_t)bl * DMODEL + c) = o;
    *(uint4*)(xr + (size_t)bl * DMODEL + c) = cvt4(o);
}

// =====================================================================
// Tensor-core GEMM v3 (tf32 mma.sync): C = A@W + bias (+res)(+relu)(+rnd)
// Both operands pre-rounded tf32 in gmem -> pure cp.async pipeline.
// CTA 128x128, 8 warps (2x4, warp tile 64x32), KC=32, 3-stage pipeline.
// =====================================================================
#define KC3    32
#define AW     36
#define BW     136
#define A_STG  (128 * AW)
#define B_STG  (KC3 * BW)
#define STG_W  (A_STG + B_STG)
#define GS3_SMEM (3 * STG_W * 4)          // 107520 bytes

__device__ __forceinline__ void gemm_body(
    const float* __restrict__ A, const float* __restrict__ Wr,
    const float* __restrict__ bias, const float* __restrict__ res,
    float* __restrict__ C, int M, int N, int K, int relu, int rnd,
    int bxx, int byy)
{
    extern __shared__ uint32_t sm[];
    uint32_t sbase = smem_u32(sm);

    int tid  = threadIdx.x;
    int lane = tid & 31;
    int wid  = tid >> 5;
    int bm = byy << 7, bn = bxx << 7;
    int warpM = (wid >> 2) * 64;
    int warpN = (wid & 3) * 32;
    int r0 = lane >> 2, c0 = lane & 3;

    int aRow[4], aC16[4], bKr[4], bC16[4];
#pragma unroll
    for (int i = 0; i < 4; i++) {
        int id = tid + i * 256;
        aRow[i] = id >> 3;  aC16[i] = id & 7;
        bKr[i]  = id >> 5;  bC16[i] = id & 31;
    }

    float acc[4][4][4];
#pragma unroll
    for (int mt = 0; mt < 4; mt++)
#pragma unroll
        for (int nt = 0; nt < 4; nt++)
#pragma unroll
            for (int r = 0; r < 4; r++) acc[mt][nt][r] = 0.f;

    int nst = K / KC3;

    auto issue_stage = [&](int st, int kc) {
        uint32_t aB = sbase + (st * STG_W) * 4;
        uint32_t bBq = sbase + (st * STG_W + A_STG) * 4;
#pragma unroll
        for (int i = 0; i < 4; i++)
            cp16(aB + (aRow[i] * AW + aC16[i] * 4) * 4,
                 A + (size_t)(bm + aRow[i]) * K + kc + aC16[i] * 4);
#pragma unroll
        for (int i = 0; i < 4; i++)
            cp16(bBq + (bKr[i] * BW + bC16[i] * 4) * 4,
                 Wr + (size_t)(kc + bKr[i]) * N + bn + bC16[i] * 4);
        CP_COMMIT();
    };

    issue_stage(0, 0);
    issue_stage(1, KC3);

    for (int s = 0; s < nst; s++) {
        int cur = s % 3;
        if (s + 1 < nst) CP_WAIT1(); else CP_WAIT0();
        __syncthreads();
        if (s + 2 < nst) issue_stage((s + 2) % 3, (s + 2) * KC3);

        const uint32_t* Ab = sm + cur * STG_W;
        const uint32_t* Bb = Ab + A_STG;
#pragma unroll
        for (int ks = 0; ks < 4; ks++) {
            int k0 = ks * 8 + c0;
            uint32_t af[4][4], bf[4][2];
#pragma unroll
            for (int mt = 0; mt < 4; mt++) {
                int m0 = warpM + mt * 16 + r0;
                af[mt][0] = Ab[m0 * AW + k0];
                af[mt][1] = Ab[(m0 + 8) * AW + k0];
                af[mt][2] = Ab[m0 * AW + k0 + 4];
                af[mt][3] = Ab[(m0 + 8) * AW + k0 + 4];
            }
#pragma unroll
            for (int nt = 0; nt < 4; nt++) {
                int n0 = warpN + nt * 8 + r0;
                bf[nt][0] = Bb[k0 * BW + n0];
                bf[nt][1] = Bb[(k0 + 4) * BW + n0];
            }
#pragma unroll
            for (int mt = 0; mt < 4; mt++)
#pragma unroll
                for (int nt = 0; nt < 4; nt++)
                    mma_tf32(acc[mt][nt], af[mt], bf[nt], acc[mt][nt]);
        }
        __syncthreads();
    }

#pragma unroll
    for (int mt = 0; mt < 4; mt++) {
        int row0 = bm + warpM + mt * 16 + r0;
#pragma unroll
        for (int h = 0; h < 2; h++) {
            int row = row0 + h * 8;
            float* crow = C + (size_t)row * N;
            const float* rrow = res ? (res + (size_t)row * N) : nullptr;
#pragma unroll
            for (int nt = 0; nt < 4; nt++) {
                int col = bn + warpN + nt * 8 + 2 * c0;
                float2 b2 = *(const float2*)(bias + col);
                float2 o;
                o.x = acc[mt][nt][h * 2 + 0] + b2.x;
                o.y = acc[mt][nt][h * 2 + 1] + b2.y;
                if (rrow) {
                    float2 r2 = *(const float2*)(rrow + col);
                    o.x += r2.x; o.y += r2.y;
                }
                if (relu) { o.x = fmaxf(o.x, 0.f); o.y = fmaxf(o.y, 0.f); }
                if (rnd)  { o.x = rnd_tf32(o.x);   o.y = rnd_tf32(o.y); }
                *(float2*)(crow + col) = o;
            }
        }
    }
}

__global__ void __launch_bounds__(256, 2) gemm_mma(
    const float* __restrict__ A, const float* __restrict__ Wr,
    const float* __restrict__ bias, const float* __restrict__ res,
    float* __restrict__ C, int M, int N, int K, int relu, int rnd)
{
    gemm_body(A, Wr, bias, res, C, M, N, K, relu, rnd,
              blockIdx.x, blockIdx.y);
}

__global__ void __launch_bounds__(256, 2) gemm_qkv(
    const float* __restrict__ x,
    const float* __restrict__ Wq, const float* __restrict__ Wk,
    const float* __restrict__ Wv,
    const float* __restrict__ bq, const float* __restrict__ bk,
    const float* __restrict__ bv,
    float* __restrict__ q, float* __restrict__ k, float* __restrict__ v)
{
    const float* W; const float* bias; float* C;
    if (blockIdx.z == 0)      { W = Wq; bias = bq; C = q; }
    else if (blockIdx.z == 1) { W = Wk; bias = bk; C = k; }
    else                      { W = Wv; bias = bv; C = v; }
    gemm_body(x, W, bias, nullptr, C, MROWS, DMODEL, DMODEL, 0, 1,
              blockIdx.x, blockIdx.y);
}

// =====================================================================
// Tensor-core flash attention (tf32 mma.sync).
// Round-13 structure (64x64, 128 thr, stride 68, dbuf K/V, Q hoisted)
// PLUS register-resident P: the S C-fragment (keys 2c0,2c0+1) is used
// directly as the PV A-fragment under a virtual-k relabeling; V row
// reads are permuted to match (key 2c0 / 2c0+1) — bit-exact, and the
// whole P smem round-trip (stores, loads, syncwarp, buffer) is gone.
// smem: Q | K0 | V0 | K1 | V1, each 64x68 words.
// =====================================================================
#define ATS 68
#define TILE_W (64 * ATS)                 // 4352 words
#define ATTN3_SMEM (5 * TILE_W * 4)       // 87040 bytes

__device__ __forceinline__ void cp_tile(
    uint32_t dstbase, const float* __restrict__ g, int tid)
{
#pragma unroll
    for (int i = 0; i < 8; i++) {
        int id  = tid + i * 128;
        int row = id >> 4, c16 = id & 15;
        cp16(dstbase + (row * ATS + c16 * 4) * 4, g + row * 64 + c16 * 4);
    }
}

__global__ void __launch_bounds__(128, 2) attn_mma(
    const float* __restrict__ q, const float* __restrict__ k,
    const float* __restrict__ v, float* __restrict__ out)
{
    extern __shared__ uint32_t smu[];
    uint32_t sbase = smem_u32(smu);
    uint32_t* Qs = smu;

    int tid  = threadIdx.x;
    int lane = tid & 31;
    int wid  = tid >> 5;
    int bh   = blockIdx.y;
    int qt   = blockIdx.x;
    int b    = bh >> 3, h = bh & 7;

    const float* Qg = q + ((size_t)bh * SEQ + qt * 64) * HDIM;
    const float* Kg = k + (size_t)bh * SEQ * HDIM;
    const float* Vg = v + (size_t)bh * SEQ * HDIM;

    // prolog: Q + K0 + V0 in one group
    cp_tile(sbase, Qg, tid);
    cp_tile(sbase + (1 * TILE_W) * 4, Kg, tid);
    cp_tile(sbase + (2 * TILE_W) * 4, Vg, tid);
    CP_COMMIT();

    int warpM = wid * 16;
    int r0 = lane >> 2, c0 = lane & 3;

    // wait prolog, then hoist Q fragments into registers (once)
    CP_WAIT0();
    __syncthreads();
    uint32_t qf[8][4];
#pragma unroll
    for (int ks = 0; ks < 8; ks++) {
        int kk = ks * 8 + c0;
        qf[ks][0] = Qs[(warpM + r0) * ATS + kk];
        qf[ks][1] = Qs[(warpM + r0 + 8) * ATS + kk];
        qf[ks][2] = Qs[(warpM + r0) * ATS + kk + 4];
        qf[ks][3] = Qs[(warpM + r0 + 8) * ATS + kk + 4];
    }

    float m0 = -1e30f, m1 = -1e30f, l0 = 0.f, l1 = 0.f;
    float o_acc[8][4];
#pragma unroll
    for (int nt = 0; nt < 8; nt++)
#pragma unroll
        for (int r = 0; r < 4; r++) o_acc[nt][r] = 0.f;

    for (int kt = 0; kt < SEQ / 64; kt++) {
        int cur = kt & 1, nb = cur ^ 1;
        if (kt > 0) {
            CP_WAIT0();
            __syncthreads();
        }
        if (kt + 1 < SEQ / 64) {
            cp_tile(sbase + ((1 + 2 * nb) * TILE_W) * 4,
                    Kg + (size_t)(kt + 1) * 64 * HDIM, tid);
            cp_tile(sbase + ((2 + 2 * nb) * TILE_W) * 4,
                    Vg + (size_t)(kt + 1) * 64 * HDIM, tid);
            CP_COMMIT();
        }
        const uint32_t* Ks = smu + (1 + 2 * cur) * TILE_W;
        const uint32_t* Vs = smu + (2 + 2 * cur) * TILE_W;

        // ---- S = Q K^T (Q from registers) ----
        float sacc[8][4];
#pragma unroll
        for (int nt = 0; nt < 8; nt++)
#pragma unroll
            for (int r = 0; r < 4; r++) sacc[nt][r] = 0.f;

#pragma unroll
        for (int ks = 0; ks < 8; ks++) {
            int kk = ks * 8 + c0;
#pragma unroll
            for (int nt = 0; nt < 8; nt++) {
                uint32_t bb[2];
                bb[0] = Ks[(nt * 8 + r0) * ATS + kk];
                bb[1] = Ks[(nt * 8 + r0) * ATS + kk + 4];
                mma_tf32(sacc[nt], qf[ks], bb, sacc[nt]);
            }
        }

        // ---- online softmax ----
        float mt0 = -1e30f, mt1 = -1e30f;
#pragma unroll
        for (int nt = 0; nt < 8; nt++) {
#pragma unroll
            for (int r = 0; r < 4; r++) sacc[nt][r] *= 0.125f;
            mt0 = fmaxf(mt0, fmaxf(sacc[nt][0], sacc[nt][1]));
            mt1 = fmaxf(mt1, fmaxf(sacc[nt][2], sacc[nt][3]));
        }
        mt0 = fmaxf(mt0, __shfl_xor_sync(0xffffffffu, mt0, 1));
        mt0 = fmaxf(mt0, __shfl_xor_sync(0xffffffffu, mt0, 2));
        mt1 = fmaxf(mt1, __shfl_xor_sync(0xffffffffu, mt1, 1));
        mt1 = fmaxf(mt1, __shfl_xor_sync(0xffffffffu, mt1, 2));

        float mn0 = fmaxf(m0, mt0), mn1 = fmaxf(m1, mt1);
        float corr0 = __expf(m0 - mn0), corr1 = __expf(m1 - mn1);
        m0 = mn0; m1 = mn1;

        // P in registers, PV A-fragment order: {p(r0,2c0), p(r0+8,2c0),
        //                                       p(r0,2c0+1), p(r0+8,2c0+1)}
        uint32_t pf[8][4];
        float rs0 = 0.f, rs1 = 0.f;
#pragma unroll
        for (int nt = 0; nt < 8; nt++) {
            float p00 = __expf(sacc[nt][0] - mn0);   // (r0,   2c0)
            float p01 = __expf(sacc[nt][1] - mn0);   // (r0,   2c0+1)
            float p10 = __expf(sacc[nt][2] - mn1);   // (r0+8, 2c0)
            float p11 = __expf(sacc[nt][3] - mn1);   // (r0+8, 2c0+1)
            rs0 += p00 + p01; rs1 += p10 + p11;
            pf[nt][0] = f2tf32(p00);
            pf[nt][1] = f2tf32(p10);
            pf[nt][2] = f2tf32(p01);
            pf[nt][3] = f2tf32(p11);
        }
        rs0 += __shfl_xor_sync(0xffffffffu, rs0, 1);
        rs0 += __shfl_xor_sync(0xffffffffu, rs0, 2);
        rs1 += __shfl_xor_sync(0xffffffffu, rs1, 1);
        rs1 += __shfl_xor_sync(0xffffffffu, rs1, 2);
        l0 = l0 * corr0 + rs0;
        l1 = l1 * corr1 + rs1;

#pragma unroll
        for (int nt = 0; nt < 8; nt++) {
            o_acc[nt][0] *= corr0; o_acc[nt][1] *= corr0;
            o_acc[nt][2] *= corr1; o_acc[nt][3] *= corr1;
        }

        // ---- O += P @ V (P from registers; V rows permuted to match:
        //      virtual k=c0 -> key 2c0, virtual k=c0+4 -> key 2c0+1) ----
#pragma unroll
        for (int ks = 0; ks < 8; ks++) {
            int kk = ks * 8;
#pragma unroll
            for (int nt = 0; nt < 8; nt++) {
                uint32_t bb[2];
                bb[0] = Vs[(kk + 2 * c0) * ATS + nt * 8 + r0];
                bb[1] = Vs[(kk + 2 * c0 + 1) * ATS + nt * 8 + r0];
                mma_tf32(o_acc[nt], pf[ks], bb, o_acc[nt]);
            }
        }
    }

    // epilogue: /l, round, scatter to [B, L, H*64 + d]
    float inv0 = 1.0f / l0, inv1 = 1.0f / l1;
    size_t row0 = (size_t)b * SEQ + qt * 64 + warpM + r0;
    float* O0 = out + row0 * DMODEL + h * HDIM;
    float* O1 = O0 + 8 * DMODEL;
#pragma unroll
    for (int nt = 0; nt < 8; nt++) {
        int col = nt * 8 + 2 * c0;
        float2 a = make_float2(rnd_tf32(o_acc[nt][0] * inv0),
                               rnd_tf32(o_acc[nt][1] * inv0));
        float2 c = make_float2(rnd_tf32(o_acc[nt][2] * inv1),
                               rnd_tf32(o_acc[nt][3] * inv1));
        *(float2*)(O0 + col) = a;
        *(float2*)(O1 + col) = c;
    }
}

// =====================================================================
// LayerNorm over last dim (512). Block per row, 128 threads.
// Dual write: out_f = fp32 (residual), out_r = tf32-rounded (gemm A).
// =====================================================================
__global__ void __launch_bounds__(128) ln_kernel(
    const float* __restrict__ in, const float* __restrict__ g,
    const float* __restrict__ b, float* __restrict__ out_f,
    float* __restrict__ out_r)
{
    int row = blockIdx.x;
    int tid = threadIdx.x;
    float4 v4 = *(const float4*)(in + (size_t)row * DMODEL + tid * 4);
    float s  = v4.x + v4.y + v4.z + v4.w;
    float sq = v4.x * v4.x + v4.y * v4.y + v4.z * v4.z + v4.w * v4.w;
#pragma unroll
    for (int off = 16; off > 0; off >>= 1) {
        s  += __shfl_xor_sync(0xffffffffu, s, off);
        sq += __shfl_xor_sync(0xffffffffu, sq, off);
    }
    __shared__ float ss[4], sqs[4];
    int wid = tid >> 5;
    if ((tid & 31) == 0) { ss[wid] = s; sqs[wid] = sq; }
    __syncthreads();
    s  = ss[0] + ss[1] + ss[2] + ss[3];
    sq = sqs[0] + sqs[1] + sqs[2] + sqs[3];
    float mu  = s * (1.0f / DMODEL);
    float var = sq * (1.0f / DMODEL) - mu * mu;
    float inv = rsqrtf(var + 1e-5f);
    float4 gv = *(const float4*)(g + tid * 4);
    float4 bv = *(const float4*)(b + tid * 4);
    float4 o;
    o.x = (v4.x - mu) * inv * gv.x + bv.x;
    o.y = (v4.y - mu) * inv * gv.y + bv.y;
    o.z = (v4.z - mu) * inv * gv.z + bv.z;
    o.w = (v4.w - mu) * inv * gv.w + bv.w;
    *(float4*)(out_f + (size_t)row * DMODEL + tid * 4) = o;
    if (out_r)
        *(uint4*)(out_r + (size_t)row * DMODEL + tid * 4) = cvt4(o);
}

// =====================================================================
// host launcher
// =====================================================================
extern "C" void kernel_launch(void* const* d_in, const int* in_sizes, int n_in,
                              void* d_out, int out_size)
{
    const int*   src  = (const int*)  d_in[0];
    const float* emb  = (const float*)d_in[1];
    const float* pe   = (const float*)d_in[2];
    const float* Wq   = (const float*)d_in[3];
    const float* bq   = (const float*)d_in[4];
    const float* Wk   = (const float*)d_in[5];
    const float* bk   = (const float*)d_in[6];
    const float* Wv   = (const float*)d_in[7];
    const float* bv   = (const float*)d_in[8];
    const float* Wo   = (const float*)d_in[9];
    const float* bo   = (const float*)d_in[10];
    const float* W1   = (const float*)d_in[11];
    const float* b1   = (const float*)d_in[12];
    const float* W2   = (const float*)d_in[13];
    const float* b2   = (const float*)d_in[14];
    const float* g1   = (const float*)d_in[15];
    const float* be1  = (const float*)d_in[16];
    const float* g2   = (const float*)d_in[17];
    const float* be2  = (const float*)d_in[18];
    float* outp = (float*)d_out;

    float *x, *xr, *q, *k, *v, *attn, *tmp, *ff, *wr;
    cudaGetSymbolAddress((void**)&x,    g_x);
    cudaGetSymbolAddress((void**)&xr,   g_xr);
    cudaGetSymbolAddress((void**)&q,    g_q);
    cudaGetSymbolAddress((void**)&k,    g_k);
    cudaGetSymbolAddress((void**)&v,    g_v);
    cudaGetSymbolAddress((void**)&attn, g_attn);
    cudaGetSymbolAddress((void**)&tmp,  g_tmp);
    cudaGetSymbolAddress((void**)&ff,   g_ff);
    cudaGetSymbolAddress((void**)&wr,   g_wr);

    cudaFuncSetAttribute(attn_mma,
                         cudaFuncAttributeMaxDynamicSharedMemorySize, ATTN3_SMEM);
    cudaFuncSetAttribute(gemm_mma,
                         cudaFuncAttributeMaxDynamicSharedMemorySize, GS3_SMEM);
    cudaFuncSetAttribute(gemm_qkv,
                         cudaFuncAttributeMaxDynamicSharedMemorySize, GS3_SMEM);

    const size_t DD6 = (size_t)NLAYERS * DMODEL * DMODEL;
    const size_t DF6 = (size_t)NLAYERS * DMODEL * DFF;
    float* WqR = wr;
    float* WkR = WqR + DD6;
    float* WvR = WkR + DD6;
    float* WoR = WvR + DD6;
    float* W1R = WoR + DD6;
    float* W2R = W1R + DF6;

    round4_kernel<<<dim3((unsigned)(DD6 / 4 / 256), 1, 4), 256>>>(
        Wq, Wk, Wv, Wo, WqR, WkR, WvR, WoR);
    round2_kernel<<<dim3((unsigned)(DF6 / 4 / 256), 1, 2), 256>>>(
        W1, W2, W1R, W2R);

    embed_kernel<<<MROWS, 128>>>(src, emb, pe, x, xr);

    dim3 gQKV(DMODEL / 128, MROWS / 128, 3);
    dim3 gProj(DMODEL / 128, MROWS / 128);
    dim3 gFF1(DFF / 128,    MROWS / 128);
    dim3 gAttn(SEQ / 64, BATCH * NHEADS);    // (32, 32)

    for (int L = 0; L < NLAYERS; L++) {
        const size_t vd  = (size_t)L * DMODEL;
        const size_t vf  = (size_t)L * DFF;
        const size_t wdd = (size_t)L * DMODEL * DMODEL;
        const size_t wdf = (size_t)L * DMODEL * DFF;

        gemm_qkv<<<gQKV, 256, GS3_SMEM>>>(xr, WqR + wdd, WkR + wdd, WvR + wdd,
                                          bq + vd, bk + vd, bv + vd, q, k, v);

        attn_mma<<<gAttn, 128, ATTN3_SMEM>>>(q, k, v, attn);

        gemm_mma<<<gProj, 256, GS3_SMEM>>>(attn, WoR + wdd, bo + vd, x, tmp,
                                           MROWS, DMODEL, DMODEL, 0, 0);
        ln_kernel<<<MROWS, 128>>>(tmp, g1 + vd, be1 + vd, x, xr);

        gemm_mma<<<gFF1, 256, GS3_SMEM>>>(xr, W1R + wdf, b1 + vf, nullptr, ff,
                                          MROWS, DFF, DMODEL, 1, 1);
        gemm_mma<<<gProj, 256, GS3_SMEM>>>(ff, W2R + wdf, b2 + vd, x, tmp,
                                           MROWS, DMODEL, DFF, 0, 0);
        ln_kernel<<<MROWS, 128>>>(tmp, g2 + vd, be2 + vd,
                                  (L == NLAYERS - 1) ? outp : x,
                                  (L == NLAYERS - 1) ? nullptr : xr);
    }
}

// round 15
// speedup vs baseline: 1.2483x; 1.0202x over previous
#include <cuda_runtime.h>
#include <cuda_bf16.h>
#include <cstdint>
#include <cstddef>

// Problem constants
#define BATCH   4
#define SEQ     2048
#define DMODEL  512
#define NHEADS  8
#define HDIM    64
#define DFF     2048
#define NLAYERS 6
#define MROWS   (BATCH * SEQ)            // 8192

// -------- scratch (device globals; no allocation allowed) --------
__device__ float g_x   [MROWS * DMODEL];   // fp32 residual stream
__device__ float g_xr  [MROWS * DMODEL];   // tf32-rounded copy (gemm A input)
__device__ float g_q   [MROWS * DMODEL];
__device__ float g_k   [MROWS * DMODEL];
__device__ float g_v   [MROWS * DMODEL];
__device__ float g_attn[MROWS * DMODEL];
__device__ float g_tmp [MROWS * DMODEL];
__device__ float g_ff  [MROWS * DFF];
// tf32-rounded weights
#define WR_TOTAL 18874368
__device__ float g_wr  [WR_TOTAL];

// ==================== helpers ====================
__device__ __forceinline__ uint32_t f2tf32(float x) {
    uint32_t u;
    asm("cvt.rna.tf32.f32 %0, %1;" : "=r"(u) : "f"(x));
    return u;
}
__device__ __forceinline__ float rnd_tf32(float x) {
    return __uint_as_float(f2tf32(x));
}
__device__ __forceinline__ uint4 cvt4(float4 v) {
    return make_uint4(f2tf32(v.x), f2tf32(v.y), f2tf32(v.z), f2tf32(v.w));
}
__device__ __forceinline__ uint32_t smem_u32(const void* p) {
    uint32_t a;
    asm("{ .reg .u64 t; cvta.to.shared.u64 t, %1; cvt.u32.u64 %0, t; }"
        : "=r"(a) : "l"(p));
    return a;
}
__device__ __forceinline__ void cp16(uint32_t dst, const void* src) {
    asm volatile("cp.async.cg.shared.global [%0], [%1], 16;"
                 :: "r"(dst), "l"(src));
}
#define CP_COMMIT() asm volatile("cp.async.commit_group;" ::: "memory")
#define CP_WAIT0()  asm volatile("cp.async.wait_group 0;" ::: "memory")
#define CP_WAIT1()  asm volatile("cp.async.wait_group 1;" ::: "memory")

// mma.sync m16n8k8 tf32: d = a*b + c  (f32 accum)
__device__ __forceinline__ void mma_tf32(
    float* d, const uint32_t* a, const uint32_t* b, const float* c)
{
    asm volatile(
        "mma.sync.aligned.m16n8k8.row.col.f32.tf32.tf32.f32 "
        "{%0,%1,%2,%3}, {%4,%5,%6,%7}, {%8,%9}, {%10,%11,%12,%13};"
        : "=f"(d[0]), "=f"(d[1]), "=f"(d[2]), "=f"(d[3])
        : "r"(a[0]), "r"(a[1]), "r"(a[2]), "r"(a[3]),
          "r"(b[0]), "r"(b[1]),
          "f"(c[0]), "f"(c[1]), "f"(c[2]), "f"(c[3]));
}

// =====================================================================
// Weight rounding passes (z-indexed, 2 launches total)
// =====================================================================
__global__ void __launch_bounds__(256) round4_kernel(
    const float* __restrict__ s0, const float* __restrict__ s1,
    const float* __restrict__ s2, const float* __restrict__ s3,
    float* __restrict__ d0, float* __restrict__ d1,
    float* __restrict__ d2, float* __restrict__ d3)
{
    const float* s; float* d;
    if (blockIdx.z == 0)      { s = s0; d = d0; }
    else if (blockIdx.z == 1) { s = s1; d = d1; }
    else if (blockIdx.z == 2) { s = s2; d = d2; }
    else                      { s = s3; d = d3; }
    int i = blockIdx.x * blockDim.x + threadIdx.x;
    float4 v = *(const float4*)(s + (size_t)i * 4);
    *(uint4*)(d + (size_t)i * 4) = cvt4(v);
}

__global__ void __launch_bounds__(256) round2_kernel(
    const float* __restrict__ s0, const float* __restrict__ s1,
    float* __restrict__ d0, float* __restrict__ d1)
{
    const float* s; float* d;
    if (blockIdx.z == 0) { s = s0; d = d0; }
    else                 { s = s1; d = d1; }
    int i = blockIdx.x * blockDim.x + threadIdx.x;
    float4 v = *(const float4*)(s + (size_t)i * 4);
    *(uint4*)(d + (size_t)i * 4) = cvt4(v);
}

// =====================================================================
// Embedding + positional encoding: dual write (fp32 + rounded)
// =====================================================================
__global__ void __launch_bounds__(128) embed_kernel(
    const int* __restrict__ src, const float* __restrict__ emb,
    const float* __restrict__ pe, float* __restrict__ xf,
    float* __restrict__ xr)
{
    int bl  = blockIdx.x;
    int l   = bl & (SEQ - 1);
    int tok = src[bl];
    int c   = threadIdx.x * 4;
    float4 e = *(const float4*)(emb + (size_t)tok * DMODEL + c);
    float4 p = *(const float4*)(pe  + (size_t)l   * DMODEL + c);
    float4 o; o.x = e.x + p.x; o.y = e.y + p.y; o.z = e.z + p.z; o.w = e.w + p.w;
    *(float4*)(xf + (size_t)bl * DMODEL + c) = o;
    *(uint4*)(xr + (size_t)bl * DMODEL + c) = cvt4(o);
}

// =====================================================================
// Tensor-core GEMM v3 (tf32 mma.sync): C = A@W + bias (+res)(+relu)(+rnd)
// Both operands pre-rounded tf32 in gmem -> pure cp.async pipeline.
// CTA 128x128, 8 warps (2x4, warp tile 64x32), KC=32, 3-stage pipeline.
// =====================================================================
#define KC3    32
#define AW     36
#define BW     136
#define A_STG  (128 * AW)
#define B_STG  (KC3 * BW)
#define STG_W  (A_STG + B_STG)
#define GS3_SMEM (3 * STG_W * 4)          // 107520 bytes

__device__ __forceinline__ void gemm_body(
    const float* __restrict__ A, const float* __restrict__ Wr,
    const float* __restrict__ bias, const float* __restrict__ res,
    float* __restrict__ C, int M, int N, int K, int relu, int rnd,
    int bxx, int byy)
{
    extern __shared__ uint32_t sm[];
    uint32_t sbase = smem_u32(sm);

    int tid  = threadIdx.x;
    int lane = tid & 31;
    int wid  = tid >> 5;
    int bm = byy << 7, bn = bxx << 7;
    int warpM = (wid >> 2) * 64;
    int warpN = (wid & 3) * 32;
    int r0 = lane >> 2, c0 = lane & 3;

    int aRow[4], aC16[4], bKr[4], bC16[4];
#pragma unroll
    for (int i = 0; i < 4; i++) {
        int id = tid + i * 256;
        aRow[i] = id >> 3;  aC16[i] = id & 7;
        bKr[i]  = id >> 5;  bC16[i] = id & 31;
    }

    float acc[4][4][4];
#pragma unroll
    for (int mt = 0; mt < 4; mt++)
#pragma unroll
        for (int nt = 0; nt < 4; nt++)
#pragma unroll
            for (int r = 0; r < 4; r++) acc[mt][nt][r] = 0.f;

    int nst = K / KC3;

    auto issue_stage = [&](int st, int kc) {
        uint32_t aB = sbase + (st * STG_W) * 4;
        uint32_t bBq = sbase + (st * STG_W + A_STG) * 4;
#pragma unroll
        for (int i = 0; i < 4; i++)
            cp16(aB + (aRow[i] * AW + aC16[i] * 4) * 4,
                 A + (size_t)(bm + aRow[i]) * K + kc + aC16[i] * 4);
#pragma unroll
        for (int i = 0; i < 4; i++)
            cp16(bBq + (bKr[i] * BW + bC16[i] * 4) * 4,
                 Wr + (size_t)(kc + bKr[i]) * N + bn + bC16[i] * 4);
        CP_COMMIT();
    };

    issue_stage(0, 0);
    issue_stage(1, KC3);

    for (int s = 0; s < nst; s++) {
        int cur = s % 3;
        if (s + 1 < nst) CP_WAIT1(); else CP_WAIT0();
        __syncthreads();
        if (s + 2 < nst) issue_stage((s + 2) % 3, (s + 2) * KC3);

        const uint32_t* Ab = sm + cur * STG_W;
        const uint32_t* Bb = Ab + A_STG;
#pragma unroll
        for (int ks = 0; ks < 4; ks++) {
            int k0 = ks * 8 + c0;
            uint32_t af[4][4], bf[4][2];
#pragma unroll
            for (int mt = 0; mt < 4; mt++) {
                int m0 = warpM + mt * 16 + r0;
                af[mt][0] = Ab[m0 * AW + k0];
                af[mt][1] = Ab[(m0 + 8) * AW + k0];
                af[mt][2] = Ab[m0 * AW + k0 + 4];
                af[mt][3] = Ab[(m0 + 8) * AW + k0 + 4];
            }
#pragma unroll
            for (int nt = 0; nt < 4; nt++) {
                int n0 = warpN + nt * 8 + r0;
                bf[nt][0] = Bb[k0 * BW + n0];
                bf[nt][1] = Bb[(k0 + 4) * BW + n0];
            }
#pragma unroll
            for (int mt = 0; mt < 4; mt++)
#pragma unroll
                for (int nt = 0; nt < 4; nt++)
                    mma_tf32(acc[mt][nt], af[mt], bf[nt], acc[mt][nt]);
        }
        __syncthreads();
    }

#pragma unroll
    for (int mt = 0; mt < 4; mt++) {
        int row0 = bm + warpM + mt * 16 + r0;
#pragma unroll
        for (int h = 0; h < 2; h++) {
            int row = row0 + h * 8;
            float* crow = C + (size_t)row * N;
            const float* rrow = res ? (res + (size_t)row * N) : nullptr;
#pragma unroll
            for (int nt = 0; nt < 4; nt++) {
                int col = bn + warpN + nt * 8 + 2 * c0;
                float2 b2 = *(const float2*)(bias + col);
                float2 o;
                o.x = acc[mt][nt][h * 2 + 0] + b2.x;
                o.y = acc[mt][nt][h * 2 + 1] + b2.y;
                if (rrow) {
                    float2 r2 = *(const float2*)(rrow + col);
                    o.x += r2.x; o.y += r2.y;
                }
                if (relu) { o.x = fmaxf(o.x, 0.f); o.y = fmaxf(o.y, 0.f); }
                if (rnd)  { o.x = rnd_tf32(o.x);   o.y = rnd_tf32(o.y); }
                *(float2*)(crow + col) = o;
            }
        }
    }
}

__global__ void __launch_bounds__(256, 2) gemm_mma(
    const float* __restrict__ A, const float* __restrict__ Wr,
    const float* __restrict__ bias, const float* __restrict__ res,
    float* __restrict__ C, int M, int N, int K, int relu, int rnd)
{
    gemm_body(A, Wr, bias, res, C, M, N, K, relu, rnd,
              blockIdx.x, blockIdx.y);
}

__global__ void __launch_bounds__(256, 2) gemm_qkv(
    const float* __restrict__ x,
    const float* __restrict__ Wq, const float* __restrict__ Wk,
    const float* __restrict__ Wv,
    const float* __restrict__ bq, const float* __restrict__ bk,
    const float* __restrict__ bv,
    float* __restrict__ q, float* __restrict__ k, float* __restrict__ v)
{
    const float* W; const float* bias; float* C;
    if (blockIdx.z == 0)      { W = Wq; bias = bq; C = q; }
    else if (blockIdx.z == 1) { W = Wk; bias = bk; C = k; }
    else                      { W = Wv; bias = bv; C = v; }
    gemm_body(x, W, bias, nullptr, C, MROWS, DMODEL, DMODEL, 0, 1,
              blockIdx.x, blockIdx.y);
}

// =====================================================================
// Tensor-core flash attention (tf32 mma.sync).
// Round-14 structure (64x64, 128 thr, stride 68, dbuf K/V, register P
// with permuted V reads) PLUS: Q fragments loaded directly from gmem
// (q is pre-rounded tf32) -> Q smem tile eliminated -> smem 69.6 KB ->
// 3 CTAs/SM (12 warps/SM, launch_bounds reg target 170).
// smem: K0 | V0 | K1 | V1, each 64x68 words.
// =====================================================================
#define ATS 68
#define TILE_W (64 * ATS)                 // 4352 words
#define ATTN3_SMEM (4 * TILE_W * 4)       // 69632 bytes

__device__ __forceinline__ void cp_tile(
    uint32_t dstbase, const float* __restrict__ g, int tid)
{
#pragma unroll
    for (int i = 0; i < 8; i++) {
        int id  = tid + i * 128;
        int row = id >> 4, c16 = id & 15;
        cp16(dstbase + (row * ATS + c16 * 4) * 4, g + row * 64 + c16 * 4);
    }
}

__global__ void __launch_bounds__(128, 3) attn_mma(
    const float* __restrict__ q, const float* __restrict__ k,
    const float* __restrict__ v, float* __restrict__ out)
{
    extern __shared__ uint32_t smu[];
    uint32_t sbase = smem_u32(smu);

    int tid  = threadIdx.x;
    int lane = tid & 31;
    int wid  = tid >> 5;
    int bh   = blockIdx.y;
    int qt   = blockIdx.x;
    int b    = bh >> 3, h = bh & 7;

    const float* Qg = q + ((size_t)bh * SEQ + qt * 64) * HDIM;
    const float* Kg = k + (size_t)bh * SEQ * HDIM;
    const float* Vg = v + (size_t)bh * SEQ * HDIM;

    // prolog: K0 + V0 via cp.async
    cp_tile(sbase + (0 * TILE_W) * 4, Kg, tid);
    cp_tile(sbase + (1 * TILE_W) * 4, Vg, tid);
    CP_COMMIT();

    int warpM = wid * 16;
    int r0 = lane >> 2, c0 = lane & 3;

    // Q fragments straight from gmem (pre-rounded tf32 bits)
    uint32_t qf[8][4];
    {
        const uint32_t* Qu = (const uint32_t*)Qg;
#pragma unroll
        for (int ks = 0; ks < 8; ks++) {
            int kk = ks * 8 + c0;
            qf[ks][0] = Qu[(warpM + r0) * HDIM + kk];
            qf[ks][1] = Qu[(warpM + r0 + 8) * HDIM + kk];
            qf[ks][2] = Qu[(warpM + r0) * HDIM + kk + 4];
            qf[ks][3] = Qu[(warpM + r0 + 8) * HDIM + kk + 4];
        }
    }

    float m0 = -1e30f, m1 = -1e30f, l0 = 0.f, l1 = 0.f;
    float o_acc[8][4];
#pragma unroll
    for (int nt = 0; nt < 8; nt++)
#pragma unroll
        for (int r = 0; r < 4; r++) o_acc[nt][r] = 0.f;

    for (int kt = 0; kt < SEQ / 64; kt++) {
        int cur = kt & 1, nb = cur ^ 1;
        CP_WAIT0();
        __syncthreads();
        if (kt + 1 < SEQ / 64) {
            cp_tile(sbase + ((2 * nb + 0) * TILE_W) * 4,
                    Kg + (size_t)(kt + 1) * 64 * HDIM, tid);
            cp_tile(sbase + ((2 * nb + 1) * TILE_W) * 4,
                    Vg + (size_t)(kt + 1) * 64 * HDIM, tid);
            CP_COMMIT();
        }
        const uint32_t* Ks = smu + (2 * cur + 0) * TILE_W;
        const uint32_t* Vs = smu + (2 * cur + 1) * TILE_W;

        // ---- S = Q K^T (Q from registers) ----
        float sacc[8][4];
#pragma unroll
        for (int nt = 0; nt < 8; nt++)
#pragma unroll
            for (int r = 0; r < 4; r++) sacc[nt][r] = 0.f;

#pragma unroll
        for (int ks = 0; ks < 8; ks++) {
            int kk = ks * 8 + c0;
#pragma unroll
            for (int nt = 0; nt < 8; nt++) {
                uint32_t bb[2];
                bb[0] = Ks[(nt * 8 + r0) * ATS + kk];
                bb[1] = Ks[(nt * 8 + r0) * ATS + kk + 4];
                mma_tf32(sacc[nt], qf[ks], bb, sacc[nt]);
            }
        }

        // ---- online softmax ----
        float mt0 = -1e30f, mt1 = -1e30f;
#pragma unroll
        for (int nt = 0; nt < 8; nt++) {
#pragma unroll
            for (int r = 0; r < 4; r++) sacc[nt][r] *= 0.125f;
            mt0 = fmaxf(mt0, fmaxf(sacc[nt][0], sacc[nt][1]));
            mt1 = fmaxf(mt1, fmaxf(sacc[nt][2], sacc[nt][3]));
        }
        mt0 = fmaxf(mt0, __shfl_xor_sync(0xffffffffu, mt0, 1));
        mt0 = fmaxf(mt0, __shfl_xor_sync(0xffffffffu, mt0, 2));
        mt1 = fmaxf(mt1, __shfl_xor_sync(0xffffffffu, mt1, 1));
        mt1 = fmaxf(mt1, __shfl_xor_sync(0xffffffffu, mt1, 2));

        float mn0 = fmaxf(m0, mt0), mn1 = fmaxf(m1, mt1);
        float corr0 = __expf(m0 - mn0), corr1 = __expf(m1 - mn1);
        m0 = mn0; m1 = mn1;

        // P in registers, PV A-fragment order (virtual-k relabeling)
        uint32_t pf[8][4];
        float rs0 = 0.f, rs1 = 0.f;
#pragma unroll
        for (int nt = 0; nt < 8; nt++) {
            float p00 = __expf(sacc[nt][0] - mn0);   // (r0,   2c0)
            float p01 = __expf(sacc[nt][1] - mn0);   // (r0,   2c0+1)
            float p10 = __expf(sacc[nt][2] - mn1);   // (r0+8, 2c0)
            float p11 = __expf(sacc[nt][3] - mn1);   // (r0+8, 2c0+1)
            rs0 += p00 + p01; rs1 += p10 + p11;
            pf[nt][0] = f2tf32(p00);
            pf[nt][1] = f2tf32(p10);
            pf[nt][2] = f2tf32(p01);
            pf[nt][3] = f2tf32(p11);
        }
        rs0 += __shfl_xor_sync(0xffffffffu, rs0, 1);
        rs0 += __shfl_xor_sync(0xffffffffu, rs0, 2);
        rs1 += __shfl_xor_sync(0xffffffffu, rs1, 1);
        rs1 += __shfl_xor_sync(0xffffffffu, rs1, 2);
        l0 = l0 * corr0 + rs0;
        l1 = l1 * corr1 + rs1;

#pragma unroll
        for (int nt = 0; nt < 8; nt++) {
            o_acc[nt][0] *= corr0; o_acc[nt][1] *= corr0;
            o_acc[nt][2] *= corr1; o_acc[nt][3] *= corr1;
        }

        // ---- O += P @ V (P from registers; V rows permuted) ----
#pragma unroll
        for (int ks = 0; ks < 8; ks++) {
            int kk = ks * 8;
#pragma unroll
            for (int nt = 0; nt < 8; nt++) {
                uint32_t bb[2];
                bb[0] = Vs[(kk + 2 * c0) * ATS + nt * 8 + r0];
                bb[1] = Vs[(kk + 2 * c0 + 1) * ATS + nt * 8 + r0];
                mma_tf32(o_acc[nt], pf[ks], bb, o_acc[nt]);
            }
        }
    }

    // epilogue: /l, round, scatter to [B, L, H*64 + d]
    float inv0 = 1.0f / l0, inv1 = 1.0f / l1;
    size_t row0 = (size_t)b * SEQ + qt * 64 + warpM + r0;
    float* O0 = out + row0 * DMODEL + h * HDIM;
    float* O1 = O0 + 8 * DMODEL;
#pragma unroll
    for (int nt = 0; nt < 8; nt++) {
        int col = nt * 8 + 2 * c0;
        float2 a = make_float2(rnd_tf32(o_acc[nt][0] * inv0),
                               rnd_tf32(o_acc[nt][1] * inv0));
        float2 c = make_float2(rnd_tf32(o_acc[nt][2] * inv1),
                               rnd_tf32(o_acc[nt][3] * inv1));
        *(float2*)(O0 + col) = a;
        *(float2*)(O1 + col) = c;
    }
}

// =====================================================================
// LayerNorm over last dim (512). Block per row, 128 threads.
// Dual write: out_f = fp32 (residual), out_r = tf32-rounded (gemm A).
// =====================================================================
__global__ void __launch_bounds__(128) ln_kernel(
    const float* __restrict__ in, const float* __restrict__ g,
    const float* __restrict__ b, float* __restrict__ out_f,
    float* __restrict__ out_r)
{
    int row = blockIdx.x;
    int tid = threadIdx.x;
    float4 v4 = *(const float4*)(in + (size_t)row * DMODEL + tid * 4);
    float s  = v4.x + v4.y + v4.z + v4.w;
    float sq = v4.x * v4.x + v4.y * v4.y + v4.z * v4.z + v4.w * v4.w;
#pragma unroll
    for (int off = 16; off > 0; off >>= 1) {
        s  += __shfl_xor_sync(0xffffffffu, s, off);
        sq += __shfl_xor_sync(0xffffffffu, sq, off);
    }
    __shared__ float ss[4], sqs[4];
    int wid = tid >> 5;
    if ((tid & 31) == 0) { ss[wid] = s; sqs[wid] = sq; }
    __syncthreads();
    s  = ss[0] + ss[1] + ss[2] + ss[3];
    sq = sqs[0] + sqs[1] + sqs[2] + sqs[3];
    float mu  = s * (1.0f / DMODEL);
    float var = sq * (1.0f / DMODEL) - mu * mu;
    float inv = rsqrtf(var + 1e-5f);
    float4 gv = *(const float4*)(g + tid * 4);
    float4 bv = *(const float4*)(b + tid * 4);
    float4 o;
    o.x = (v4.x - mu) * inv * gv.x + bv.x;
    o.y = (v4.y - mu) * inv * gv.y + bv.y;
    o.z = (v4.z - mu) * inv * gv.z + bv.z;
    o.w = (v4.w - mu) * inv * gv.w + bv.w;
    *(float4*)(out_f + (size_t)row * DMODEL + tid * 4) = o;
    if (out_r)
        *(uint4*)(out_r + (size_t)row * DMODEL + tid * 4) = cvt4(o);
}

// =====================================================================
// host launcher
// =====================================================================
extern "C" void kernel_launch(void* const* d_in, const int* in_sizes, int n_in,
                              void* d_out, int out_size)
{
    const int*   src  = (const int*)  d_in[0];
    const float* emb  = (const float*)d_in[1];
    const float* pe   = (const float*)d_in[2];
    const float* Wq   = (const float*)d_in[3];
    const float* bq   = (const float*)d_in[4];
    const float* Wk   = (const float*)d_in[5];
    const float* bk   = (const float*)d_in[6];
    const float* Wv   = (const float*)d_in[7];
    const float* bv   = (const float*)d_in[8];
    const float* Wo   = (const float*)d_in[9];
    const float* bo   = (const float*)d_in[10];
    const float* W1   = (const float*)d_in[11];
    const float* b1   = (const float*)d_in[12];
    const float* W2   = (const float*)d_in[13];
    const float* b2   = (const float*)d_in[14];
    const float* g1   = (const float*)d_in[15];
    const float* be1  = (const float*)d_in[16];
    const float* g2   = (const float*)d_in[17];
    const float* be2  = (const float*)d_in[18];
    float* outp = (float*)d_out;

    float *x, *xr, *q, *k, *v, *attn, *tmp, *ff, *wr;
    cudaGetSymbolAddress((void**)&x,    g_x);
    cudaGetSymbolAddress((void**)&xr,   g_xr);
    cudaGetSymbolAddress((void**)&q,    g_q);
    cudaGetSymbolAddress((void**)&k,    g_k);
    cudaGetSymbolAddress((void**)&v,    g_v);
    cudaGetSymbolAddress((void**)&attn, g_attn);
    cudaGetSymbolAddress((void**)&tmp,  g_tmp);
    cudaGetSymbolAddress((void**)&ff,   g_ff);
    cudaGetSymbolAddress((void**)&wr,   g_wr);

    cudaFuncSetAttribute(attn_mma,
                         cudaFuncAttributeMaxDynamicSharedMemorySize, ATTN3_SMEM);
    cudaFuncSetAttribute(gemm_mma,
                         cudaFuncAttributeMaxDynamicSharedMemorySize, GS3_SMEM);
    cudaFuncSetAttribute(gemm_qkv,
                         cudaFuncAttributeMaxDynamicSharedMemorySize, GS3_SMEM);

    const size_t DD6 = (size_t)NLAYERS * DMODEL * DMODEL;
    const size_t DF6 = (size_t)NLAYERS * DMODEL * DFF;
    float* WqR = wr;
    float* WkR = WqR + DD6;
    float* WvR = WkR + DD6;
    float* WoR = WvR + DD6;
    float* W1R = WoR + DD6;
    float* W2R = W1R + DF6;

    round4_kernel<<<dim3((unsigned)(DD6 / 4 / 256), 1, 4), 256>>>(
        Wq, Wk, Wv, Wo, WqR, WkR, WvR, WoR);
    round2_kernel<<<dim3((unsigned)(DF6 / 4 / 256), 1, 2), 256>>>(
        W1, W2, W1R, W2R);

    embed_kernel<<<MROWS, 128>>>(src, emb, pe, x, xr);

    dim3 gQKV(DMODEL / 128, MROWS / 128, 3);
    dim3 gProj(DMODEL / 128, MROWS / 128);
    dim3 gFF1(DFF / 128,    MROWS / 128);
    dim3 gAttn(SEQ / 64, BATCH * NHEADS);    // (32, 32)

    for (int L = 0; L < NLAYERS; L++) {
        const size_t vd  = (size_t)L * DMODEL;
        const size_t vf  = (size_t)L * DFF;
        const size_t wdd = (size_t)L * DMODEL * DMODEL;
        const size_t wdf = (size_t)L * DMODEL * DFF;

        gemm_qkv<<<gQKV, 256, GS3_SMEM>>>(xr, WqR + wdd, WkR + wdd, WvR + wdd,
                                          bq + vd, bk + vd, bv + vd, q, k, v);

        attn_mma<<<gAttn, 128, ATTN3_SMEM>>>(q, k, v, attn);

        gemm_mma<<<gProj, 256, GS3_SMEM>>>(attn, WoR + wdd, bo + vd, x, tmp,
                                           MROWS, DMODEL, DMODEL, 0, 0);
        ln_kernel<<<MROWS, 128>>>(tmp, g1 + vd, be1 + vd, x, xr);

        gemm_mma<<<gFF1, 256, GS3_SMEM>>>(xr, W1R + wdf, b1 + vf, nullptr, ff,
                                          MROWS, DFF, DMODEL, 1, 1);
        gemm_mma<<<gProj, 256, GS3_SMEM>>>(ff, W2R + wdf, b2 + vd, x, tmp,
                                           MROWS, DMODEL, DFF, 0, 0);
        ln_kernel<<<MROWS, 128>>>(tmp, g2 + vd, be2 + vd,
                                  (L == NLAYERS - 1) ? outp : x,
                                  (L == NLAYERS - 1) ? nullptr : xr);
    }
}

// round 16
// speedup vs baseline: 1.6713x; 1.3389x over previous
#include <cuda_runtime.h>
#include <cuda_fp16.h>
#include <cstdint>
#include <cstddef>

// Problem constants
#define BATCH   4
#define SEQ     2048
#define DMODEL  512
#define NHEADS  8
#define HDIM    64
#define DFF     2048
#define NLAYERS 6
#define MROWS   (BATCH * SEQ)            // 8192

// -------- scratch (device globals; no allocation allowed) --------
__device__ float    g_x   [MROWS * DMODEL];     // fp32 residual stream
__device__ uint32_t g_xh  [MROWS * DMODEL / 2]; // half2-packed x (gemm A)
__device__ float    g_q   [MROWS * DMODEL];     // tf32 fp32 (attention)
__device__ float    g_k   [MROWS * DMODEL];
__device__ float    g_v   [MROWS * DMODEL];
__device__ uint32_t g_ath [MROWS * DMODEL / 2]; // attn out, half2 packed
__device__ float    g_tmp [MROWS * DMODEL];
__device__ uint32_t g_ffh [MROWS * DFF / 2];    // ff out, half2 packed
// half2-packed weights: word(k',n) = (W[2k'][n], W[2k'+1][n])
#define WH_TOTAL 9437184
__device__ uint32_t g_wh  [WH_TOTAL];

// ==================== helpers ====================
__device__ __forceinline__ uint32_t f2tf32(float x) {
    uint32_t u;
    asm("cvt.rna.tf32.f32 %0, %1;" : "=r"(u) : "f"(x));
    return u;
}
__device__ __forceinline__ float rnd_tf32(float x) {
    return __uint_as_float(f2tf32(x));
}
__device__ __forceinline__ uint32_t packh2(float a, float b) {
    __half2 h = __floats2half2_rn(a, b);
    return *reinterpret_cast<uint32_t*>(&h);
}
__device__ __forceinline__ uint32_t smem_u32(const void* p) {
    uint32_t a;
    asm("{ .reg .u64 t; cvta.to.shared.u64 t, %1; cvt.u32.u64 %0, t; }"
        : "=r"(a) : "l"(p));
    return a;
}
__device__ __forceinline__ void cp16(uint32_t dst, const void* src) {
    asm volatile("cp.async.cg.shared.global [%0], [%1], 16;"
                 :: "r"(dst), "l"(src));
}
#define CP_COMMIT() asm volatile("cp.async.commit_group;" ::: "memory")
#define CP_WAIT0()  asm volatile("cp.async.wait_group 0;" ::: "memory")
#define CP_WAIT1()  asm volatile("cp.async.wait_group 1;" ::: "memory")

// mma m16n8k16 f16 inputs, f32 accum
__device__ __forceinline__ void mma_f16(
    float* d, const uint32_t* a, const uint32_t* b, const float* c)
{
    asm volatile(
        "mma.sync.aligned.m16n8k16.row.col.f32.f16.f16.f32 "
        "{%0,%1,%2,%3}, {%4,%5,%6,%7}, {%8,%9}, {%10,%11,%12,%13};"
        : "=f"(d[0]), "=f"(d[1]), "=f"(d[2]), "=f"(d[3])
        : "r"(a[0]), "r"(a[1]), "r"(a[2]), "r"(a[3]),
          "r"(b[0]), "r"(b[1]),
          "f"(c[0]), "f"(c[1]), "f"(c[2]), "f"(c[3]));
}
// mma m16n8k8 tf32 (attention)
__device__ __forceinline__ void mma_tf32(
    float* d, const uint32_t* a, const uint32_t* b, const float* c)
{
    asm volatile(
        "mma.sync.aligned.m16n8k8.row.col.f32.tf32.tf32.f32 "
        "{%0,%1,%2,%3}, {%4,%5,%6,%7}, {%8,%9}, {%10,%11,%12,%13};"
        : "=f"(d[0]), "=f"(d[1]), "=f"(d[2]), "=f"(d[3])
        : "r"(a[0]), "r"(a[1]), "r"(a[2]), "r"(a[3]),
          "r"(b[0]), "r"(b[1]),
          "f"(c[0]), "f"(c[1]), "f"(c[2]), "f"(c[3]));
}

// =====================================================================
// Weight packing: fp32 [K][N] -> half2 words [K/2][N]
// z = tensor id, y = layer, x*256*4 = word offset
// =====================================================================
__global__ void __launch_bounds__(256) pack_kernel(
    const float* __restrict__ s0, const float* __restrict__ s1,
    const float* __restrict__ s2, const float* __restrict__ s3,
    const float* __restrict__ s4, const float* __restrict__ s5,
    uint32_t* __restrict__ wh)
{
    int t = blockIdx.z;
    const float* s;
    if (t == 0) s = s0; else if (t == 1) s = s1; else if (t == 2) s = s2;
    else if (t == 3) s = s3; else if (t == 4) s = s4; else s = s5;
    int K = (t == 5) ? DFF : DMODEL;
    int N = (t == 4) ? DFF : DMODEL;
    int wpl = (K >> 1) * N;                       // words per layer
    const size_t seg[6] = {0, 786432, 1572864, 2359296, 3145728, 6291456};
    int w = (blockIdx.x * 256 + threadIdx.x) * 4;
    if (w >= wpl) return;
    int kp = w / N, n = w % N;
    const float* sl = s + (size_t)blockIdx.y * K * N;
    float4 lo = *(const float4*)(sl + (size_t)(2 * kp) * N + n);
    float4 hi = *(const float4*)(sl + (size_t)(2 * kp + 1) * N + n);
    uint4 o = make_uint4(packh2(lo.x, hi.x), packh2(lo.y, hi.y),
                         packh2(lo.z, hi.z), packh2(lo.w, hi.w));
    *(uint4*)(wh + seg[t] + (size_t)blockIdx.y * wpl + w) = o;
}

// =====================================================================
// Embedding + positional encoding: dual write (fp32 + half2)
// =====================================================================
__global__ void __launch_bounds__(128) embed_kernel(
    const int* __restrict__ src, const float* __restrict__ emb,
    const float* __restrict__ pe, float* __restrict__ xf,
    uint32_t* __restrict__ xh)
{
    int bl  = blockIdx.x;
    int l   = bl & (SEQ - 1);
    int tok = src[bl];
    int c   = threadIdx.x * 4;
    float4 e = *(const float4*)(emb + (size_t)tok * DMODEL + c);
    float4 p = *(const float4*)(pe  + (size_t)l   * DMODEL + c);
    float4 o; o.x = e.x + p.x; o.y = e.y + p.y; o.z = e.z + p.z; o.w = e.w + p.w;
    *(float4*)(xf + (size_t)bl * DMODEL + c) = o;
    uint2 h = make_uint2(packh2(o.x, o.y), packh2(o.z, o.w));
    *(uint2*)(xh + (size_t)bl * (DMODEL / 2) + threadIdx.x * 2) = h;
}

// =====================================================================
// fp16 tensor-core GEMM: C = A@W + bias (+res)(+relu), out fp32 or half2
// A: half2-packed rows [M][K/2]; W: half2-packed [K/2][N] (g_wh).
// CTA 128x128, 8 warps (2x4, warp tile 64x32), KC=32 k (16 packed),
// 3-stage cp.async pipeline. A smem [128][20], B smem [16][136],
// both conflict-free for m16n8k16 fragment loads.
// =====================================================================
#define AWH    20
#define BWH    136
#define A_STGH (128 * AWH)                // 2560 words
#define B_STGH (16 * BWH)                 // 2176 words
#define STG_WH (A_STGH + B_STGH)          // 4736 words
#define GSH_SMEM (3 * STG_WH * 4)         // 56832 bytes

__device__ __forceinline__ void gemm_body(
    const uint32_t* __restrict__ A, const uint32_t* __restrict__ Wh,
    const float* __restrict__ bias, const float* __restrict__ res,
    float* __restrict__ Cf, uint32_t* __restrict__ Ch,
    int M, int N, int K, int relu, int rnd, int bxx, int byy)
{
    extern __shared__ uint32_t sm[];
    uint32_t sbase = smem_u32(sm);

    int tid  = threadIdx.x;
    int lane = tid & 31;
    int wid  = tid >> 5;
    int bm = byy << 7, bn = bxx << 7;
    int warpM = (wid >> 2) * 64;
    int warpN = (wid & 3) * 32;
    int r0 = lane >> 2, c0 = lane & 3;
    int K2 = K >> 1;

    float acc[4][4][4];
#pragma unroll
    for (int mt = 0; mt < 4; mt++)
#pragma unroll
        for (int nt = 0; nt < 4; nt++)
#pragma unroll
            for (int r = 0; r < 4; r++) acc[mt][nt][r] = 0.f;

    int nst = K >> 5;                      // stages of 32 k (16 packed)

    auto issue_stage = [&](int st, int kc2) {
        uint32_t aB = sbase + (st * STG_WH) * 4;
        uint32_t bB = sbase + (st * STG_WH + A_STGH) * 4;
#pragma unroll
        for (int i = 0; i < 2; i++) {      // A: 512 chunks
            int id = tid + i * 256;
            int row = id >> 2, c16 = id & 3;
            cp16(aB + (row * AWH + c16 * 4) * 4,
                 A + (size_t)row * K2 + kc2 + c16 * 4);
        }
#pragma unroll
        for (int i = 0; i < 2; i++) {      // B: 512 chunks
            int id = tid + i * 256;
            int kr = id >> 5, c16 = id & 31;
            cp16(bB + (kr * BWH + c16 * 4) * 4,
                 Wh + (size_t)(kc2 + kr) * N + bn + c16 * 4);
        }
        CP_COMMIT();
    };

    const uint32_t* Abase = A + (size_t)bm * K2;
    A = Abase;

    issue_stage(0, 0);
    issue_stage(1, 16);

    for (int s = 0; s < nst; s++) {
        int cur = s % 3;
        if (s + 1 < nst) CP_WAIT1(); else CP_WAIT0();
        __syncthreads();
        if (s + 2 < nst) issue_stage((s + 2) % 3, (s + 2) * 16);

        const uint32_t* Ab = sm + cur * STG_WH;
        const uint32_t* Bb = Ab + A_STGH;
#pragma unroll
        for (int ks = 0; ks < 2; ks++) {
            int kb = ks * 8;
            uint32_t af[4][4], bf[4][2];
#pragma unroll
            for (int mt = 0; mt < 4; mt++) {
                int m0 = warpM + mt * 16 + r0;
                af[mt][0] = Ab[m0 * AWH + kb + c0];
                af[mt][1] = Ab[(m0 + 8) * AWH + kb + c0];
                af[mt][2] = Ab[m0 * AWH + kb + c0 + 4];
                af[mt][3] = Ab[(m0 + 8) * AWH + kb + c0 + 4];
            }
#pragma unroll
            for (int nt = 0; nt < 4; nt++) {
                int n0 = warpN + nt * 8 + r0;
                bf[nt][0] = Bb[(kb + c0) * BWH + n0];
                bf[nt][1] = Bb[(kb + c0 + 4) * BWH + n0];
            }
#pragma unroll
            for (int mt = 0; mt < 4; mt++)
#pragma unroll
                for (int nt = 0; nt < 4; nt++)
                    mma_f16(acc[mt][nt], af[mt], bf[nt], acc[mt][nt]);
        }
        __syncthreads();
    }

#pragma unroll
    for (int mt = 0; mt < 4; mt++) {
        int row0 = bm + warpM + mt * 16 + r0;
#pragma unroll
        for (int h = 0; h < 2; h++) {
            int row = row0 + h * 8;
            const float* rrow = res ? (res + (size_t)row * N) : nullptr;
#pragma unroll
            for (int nt = 0; nt < 4; nt++) {
                int col = bn + warpN + nt * 8 + 2 * c0;
                float2 b2 = *(const float2*)(bias + col);
                float2 o;
                o.x = acc[mt][nt][h * 2 + 0] + b2.x;
                o.y = acc[mt][nt][h * 2 + 1] + b2.y;
                if (rrow) {
                    float2 r2 = *(const float2*)(rrow + col);
                    o.x += r2.x; o.y += r2.y;
                }
                if (relu) { o.x = fmaxf(o.x, 0.f); o.y = fmaxf(o.y, 0.f); }
                if (Ch) {
                    Ch[(size_t)row * (N >> 1) + (col >> 1)] = packh2(o.x, o.y);
                } else {
                    if (rnd) { o.x = rnd_tf32(o.x); o.y = rnd_tf32(o.y); }
                    *(float2*)(Cf + (size_t)row * N + col) = o;
                }
            }
        }
    }
}

__global__ void __launch_bounds__(256, 2) gemm_mma(
    const uint32_t* __restrict__ A, const uint32_t* __restrict__ Wh,
    const float* __restrict__ bias, const float* __restrict__ res,
    float* __restrict__ Cf, uint32_t* __restrict__ Ch,
    int M, int N, int K, int relu, int rnd)
{
    gemm_body(A, Wh, bias, res, Cf, Ch, M, N, K, relu, rnd,
              blockIdx.x, blockIdx.y);
}

__global__ void __launch_bounds__(256, 2) gemm_qkv(
    const uint32_t* __restrict__ x,
    const uint32_t* __restrict__ Wq, const uint32_t* __restrict__ Wk,
    const uint32_t* __restrict__ Wv,
    const float* __restrict__ bq, const float* __restrict__ bk,
    const float* __restrict__ bv,
    float* __restrict__ q, float* __restrict__ k, float* __restrict__ v)
{
    const uint32_t* W; const float* bias; float* C;
    if (blockIdx.z == 0)      { W = Wq; bias = bq; C = q; }
    else if (blockIdx.z == 1) { W = Wk; bias = bk; C = k; }
    else                      { W = Wv; bias = bv; C = v; }
    gemm_body(x, W, bias, nullptr, C, nullptr, MROWS, DMODEL, DMODEL, 0, 1,
              blockIdx.x, blockIdx.y);
}

// =====================================================================
// Tensor-core flash attention (tf32 mma.sync) — round-15 structure,
// unchanged except the epilogue packs output pairs to half2 (Wo input).
// smem: K0 | V0 | K1 | V1, each 64x68 words. 3 CTAs/SM.
// =====================================================================
#define ATS 68
#define TILE_W (64 * ATS)                 // 4352 words
#define ATTN3_SMEM (4 * TILE_W * 4)       // 69632 bytes

__device__ __forceinline__ void cp_tile(
    uint32_t dstbase, const float* __restrict__ g, int tid)
{
#pragma unroll
    for (int i = 0; i < 8; i++) {
        int id  = tid + i * 128;
        int row = id >> 4, c16 = id & 15;
        cp16(dstbase + (row * ATS + c16 * 4) * 4, g + row * 64 + c16 * 4);
    }
}

__global__ void __launch_bounds__(128, 3) attn_mma(
    const float* __restrict__ q, const float* __restrict__ k,
    const float* __restrict__ v, uint32_t* __restrict__ outh)
{
    extern __shared__ uint32_t smu[];
    uint32_t sbase = smem_u32(smu);

    int tid  = threadIdx.x;
    int lane = tid & 31;
    int wid  = tid >> 5;
    int bh   = blockIdx.y;
    int qt   = blockIdx.x;
    int b    = bh >> 3, h = bh & 7;

    const float* Qg = q + ((size_t)bh * SEQ + qt * 64) * HDIM;
    const float* Kg = k + (size_t)bh * SEQ * HDIM;
    const float* Vg = v + (size_t)bh * SEQ * HDIM;

    cp_tile(sbase + (0 * TILE_W) * 4, Kg, tid);
    cp_tile(sbase + (1 * TILE_W) * 4, Vg, tid);
    CP_COMMIT();

    int warpM = wid * 16;
    int r0 = lane >> 2, c0 = lane & 3;

    uint32_t qf[8][4];
    {
        const uint32_t* Qu = (const uint32_t*)Qg;
#pragma unroll
        for (int ks = 0; ks < 8; ks++) {
            int kk = ks * 8 + c0;
            qf[ks][0] = Qu[(warpM + r0) * HDIM + kk];
            qf[ks][1] = Qu[(warpM + r0 + 8) * HDIM + kk];
            qf[ks][2] = Qu[(warpM + r0) * HDIM + kk + 4];
            qf[ks][3] = Qu[(warpM + r0 + 8) * HDIM + kk + 4];
        }
    }

    float m0 = -1e30f, m1 = -1e30f, l0 = 0.f, l1 = 0.f;
    float o_acc[8][4];
#pragma unroll
    for (int nt = 0; nt < 8; nt++)
#pragma unroll
        for (int r = 0; r < 4; r++) o_acc[nt][r] = 0.f;

    for (int kt = 0; kt < SEQ / 64; kt++) {
        int cur = kt & 1, nb = cur ^ 1;
        CP_WAIT0();
        __syncthreads();
        if (kt + 1 < SEQ / 64) {
            cp_tile(sbase + ((2 * nb + 0) * TILE_W) * 4,
                    Kg + (size_t)(kt + 1) * 64 * HDIM, tid);
            cp_tile(sbase + ((2 * nb + 1) * TILE_W) * 4,
                    Vg + (size_t)(kt + 1) * 64 * HDIM, tid);
            CP_COMMIT();
        }
        const uint32_t* Ks = smu + (2 * cur + 0) * TILE_W;
        const uint32_t* Vs = smu + (2 * cur + 1) * TILE_W;

        float sacc[8][4];
#pragma unroll
        for (int nt = 0; nt < 8; nt++)
#pragma unroll
            for (int r = 0; r < 4; r++) sacc[nt][r] = 0.f;

#pragma unroll
        for (int ks = 0; ks < 8; ks++) {
            int kk = ks * 8 + c0;
#pragma unroll
            for (int nt = 0; nt < 8; nt++) {
                uint32_t bb[2];
                bb[0] = Ks[(nt * 8 + r0) * ATS + kk];
                bb[1] = Ks[(nt * 8 + r0) * ATS + kk + 4];
                mma_tf32(sacc[nt], qf[ks], bb, sacc[nt]);
            }
        }

        float mt0 = -1e30f, mt1 = -1e30f;
#pragma unroll
        for (int nt = 0; nt < 8; nt++) {
#pragma unroll
            for (int r = 0; r < 4; r++) sacc[nt][r] *= 0.125f;
            mt0 = fmaxf(mt0, fmaxf(sacc[nt][0], sacc[nt][1]));
            mt1 = fmaxf(mt1, fmaxf(sacc[nt][2], sacc[nt][3]));
        }
        mt0 = fmaxf(mt0, __shfl_xor_sync(0xffffffffu, mt0, 1));
        mt0 = fmaxf(mt0, __shfl_xor_sync(0xffffffffu, mt0, 2));
        mt1 = fmaxf(mt1, __shfl_xor_sync(0xffffffffu, mt1, 1));
        mt1 = fmaxf(mt1, __shfl_xor_sync(0xffffffffu, mt1, 2));

        float mn0 = fmaxf(m0, mt0), mn1 = fmaxf(m1, mt1);
        float corr0 = __expf(m0 - mn0), corr1 = __expf(m1 - mn1);
        m0 = mn0; m1 = mn1;

        uint32_t pf[8][4];
        float rs0 = 0.f, rs1 = 0.f;
#pragma unroll
        for (int nt = 0; nt < 8; nt++) {
            float p00 = __expf(sacc[nt][0] - mn0);
            float p01 = __expf(sacc[nt][1] - mn0);
            float p10 = __expf(sacc[nt][2] - mn1);
            float p11 = __expf(sacc[nt][3] - mn1);
            rs0 += p00 + p01; rs1 += p10 + p11;
            pf[nt][0] = f2tf32(p00);
            pf[nt][1] = f2tf32(p10);
            pf[nt][2] = f2tf32(p01);
            pf[nt][3] = f2tf32(p11);
        }
        rs0 += __shfl_xor_sync(0xffffffffu, rs0, 1);
        rs0 += __shfl_xor_sync(0xffffffffu, rs0, 2);
        rs1 += __shfl_xor_sync(0xffffffffu, rs1, 1);
        rs1 += __shfl_xor_sync(0xffffffffu, rs1, 2);
        l0 = l0 * corr0 + rs0;
        l1 = l1 * corr1 + rs1;

#pragma unroll
        for (int nt = 0; nt < 8; nt++) {
            o_acc[nt][0] *= corr0; o_acc[nt][1] *= corr0;
            o_acc[nt][2] *= corr1; o_acc[nt][3] *= corr1;
        }

#pragma unroll
        for (int ks = 0; ks < 8; ks++) {
            int kk = ks * 8;
#pragma unroll
            for (int nt = 0; nt < 8; nt++) {
                uint32_t bb[2];
                bb[0] = Vs[(kk + 2 * c0) * ATS + nt * 8 + r0];
                bb[1] = Vs[(kk + 2 * c0 + 1) * ATS + nt * 8 + r0];
                mma_tf32(o_acc[nt], pf[ks], bb, o_acc[nt]);
            }
        }
    }

    // epilogue: /l, pack half2, scatter to [B, L, (H*64+d)/2]
    float inv0 = 1.0f / l0, inv1 = 1.0f / l1;
    size_t row0 = (size_t)b * SEQ + qt * 64 + warpM + r0;
    uint32_t* O0 = outh + row0 * (DMODEL / 2) + h * (HDIM / 2);
    uint32_t* O1 = O0 + 8 * (DMODEL / 2);
#pragma unroll
    for (int nt = 0; nt < 8; nt++) {
        int w = nt * 4 + c0;
        O0[w] = packh2(o_acc[nt][0] * inv0, o_acc[nt][1] * inv0);
        O1[w] = packh2(o_acc[nt][2] * inv1, o_acc[nt][3] * inv1);
    }
}

// =====================================================================
// LayerNorm over last dim (512). Block per row, 128 threads.
// Dual write: out_f = fp32 (residual), out_h = half2 (gemm A input).
// =====================================================================
__global__ void __launch_bounds__(128) ln_kernel(
    const float* __restrict__ in, const float* __restrict__ g,
    const float* __restrict__ b, float* __restrict__ out_f,
    uint32_t* __restrict__ out_h)
{
    int row = blockIdx.x;
    int tid = threadIdx.x;
    float4 v4 = *(const float4*)(in + (size_t)row * DMODEL + tid * 4);
    float s  = v4.x + v4.y + v4.z + v4.w;
    float sq = v4.x * v4.x + v4.y * v4.y + v4.z * v4.z + v4.w * v4.w;
#pragma unroll
    for (int off = 16; off > 0; off >>= 1) {
        s  += __shfl_xor_sync(0xffffffffu, s, off);
        sq += __shfl_xor_sync(0xffffffffu, sq, off);
    }
    __shared__ float ss[4], sqs[4];
    int wid = tid >> 5;
    if ((tid & 31) == 0) { ss[wid] = s; sqs[wid] = sq; }
    __syncthreads();
    s  = ss[0] + ss[1] + ss[2] + ss[3];
    sq = sqs[0] + sqs[1] + sqs[2] + sqs[3];
    float mu  = s * (1.0f / DMODEL);
    float var = sq * (1.0f / DMODEL) - mu * mu;
    float inv = rsqrtf(var + 1e-5f);
    float4 gv = *(const float4*)(g + tid * 4);
    float4 bv = *(const float4*)(b + tid * 4);
    float4 o;
    o.x = (v4.x - mu) * inv * gv.x + bv.x;
    o.y = (v4.y - mu) * inv * gv.y + bv.y;
    o.z = (v4.z - mu) * inv * gv.z + bv.z;
    o.w = (v4.w - mu) * inv * gv.w + bv.w;
    *(float4*)(out_f + (size_t)row * DMODEL + tid * 4) = o;
    if (out_h) {
        uint2 hw = make_uint2(packh2(o.x, o.y), packh2(o.z, o.w));
        *(uint2*)(out_h + (size_t)row * (DMODEL / 2) + tid * 2) = hw;
    }
}

// =====================================================================
// host launcher
// =====================================================================
extern "C" void kernel_launch(void* const* d_in, const int* in_sizes, int n_in,
                              void* d_out, int out_size)
{
    const int*   src  = (const int*)  d_in[0];
    const float* emb  = (const float*)d_in[1];
    const float* pe   = (const float*)d_in[2];
    const float* Wq   = (const float*)d_in[3];
    const float* bq   = (const float*)d_in[4];
    const float* Wk   = (const float*)d_in[5];
    const float* bk   = (const float*)d_in[6];
    const float* Wv   = (const float*)d_in[7];
    const float* bv   = (const float*)d_in[8];
    const float* Wo   = (const float*)d_in[9];
    const float* bo   = (const float*)d_in[10];
    const float* W1   = (const float*)d_in[11];
    const float* b1   = (const float*)d_in[12];
    const float* W2   = (const float*)d_in[13];
    const float* b2   = (const float*)d_in[14];
    const float* g1   = (const float*)d_in[15];
    const float* be1  = (const float*)d_in[16];
    const float* g2   = (const float*)d_in[17];
    const float* be2  = (const float*)d_in[18];
    float* outp = (float*)d_out;

    float *x, *q, *k, *v, *tmp;
    uint32_t *xh, *ath, *ffh, *wh;
    cudaGetSymbolAddress((void**)&x,    g_x);
    cudaGetSymbolAddress((void**)&xh,   g_xh);
    cudaGetSymbolAddress((void**)&q,    g_q);
    cudaGetSymbolAddress((void**)&k,    g_k);
    cudaGetSymbolAddress((void**)&v,    g_v);
    cudaGetSymbolAddress((void**)&ath,  g_ath);
    cudaGetSymbolAddress((void**)&tmp,  g_tmp);
    cudaGetSymbolAddress((void**)&ffh,  g_ffh);
    cudaGetSymbolAddress((void**)&wh,   g_wh);

    cudaFuncSetAttribute(attn_mma,
                         cudaFuncAttributeMaxDynamicSharedMemorySize, ATTN3_SMEM);
    cudaFuncSetAttribute(gemm_mma,
                         cudaFuncAttributeMaxDynamicSharedMemorySize, GSH_SMEM);
    cudaFuncSetAttribute(gemm_qkv,
                         cudaFuncAttributeMaxDynamicSharedMemorySize, GSH_SMEM);

    // packed weight segments (words)
    uint32_t* WqH = wh;
    uint32_t* WkH = wh + 786432;
    uint32_t* WvH = wh + 1572864;
    uint32_t* WoH = wh + 2359296;
    uint32_t* W1H = wh + 3145728;
    uint32_t* W2H = wh + 6291456;
    const size_t wplD = 131072;            // (512/2)*512
    const size_t wplF = 524288;            // dxff / ffxd

    pack_kernel<<<dim3(512, NLAYERS, 6), 256>>>(Wq, Wk, Wv, Wo, W1, W2, wh);

    embed_kernel<<<MROWS, 128>>>(src, emb, pe, x, xh);

    dim3 gQKV(DMODEL / 128, MROWS / 128, 3);
    dim3 gProj(DMODEL / 128, MROWS / 128);
    dim3 gFF1(DFF / 128,    MROWS / 128);
    dim3 gAttn(SEQ / 64, BATCH * NHEADS);

    for (int L = 0; L < NLAYERS; L++) {
        const size_t vd  = (size_t)L * DMODEL;
        const size_t vf  = (size_t)L * DFF;

        gemm_qkv<<<gQKV, 256, GSH_SMEM>>>(xh, WqH + L * wplD, WkH + L * wplD,
                                          WvH + L * wplD,
                                          bq + vd, bk + vd, bv + vd, q, k, v);

        attn_mma<<<gAttn, 128, ATTN3_SMEM>>>(q, k, v, ath);

        gemm_mma<<<gProj, 256, GSH_SMEM>>>(ath, WoH + L * wplD, bo + vd, x,
                                           tmp, nullptr,
                                           MROWS, DMODEL, DMODEL, 0, 0);
        ln_kernel<<<MROWS, 128>>>(tmp, g1 + vd, be1 + vd, x, xh);

        gemm_mma<<<gFF1, 256, GSH_SMEM>>>(xh, W1H + L * wplF, b1 + vf, nullptr,
                                          nullptr, ffh,
                                          MROWS, DFF, DMODEL, 1, 0);
        gemm_mma<<<gProj, 256, GSH_SMEM>>>(ffh, W2H + L * wplF, b2 + vd, x,
                                           tmp, nullptr,
                                           MROWS, DMODEL, DFF, 0, 0);
        ln_kernel<<<MROWS, 128>>>(tmp, g2 + vd, be2 + vd,
                                  (L == NLAYERS - 1) ? outp : x,
                                  (L == NLAYERS - 1) ? nullptr : xh);
    }
}

// round 17
// speedup vs baseline: 1.8620x; 1.1141x over previous
#include <cuda_runtime.h>
#include <cuda_fp16.h>
#include <cstdint>
#include <cstddef>

// Problem constants
#define BATCH   4
#define SEQ     2048
#define DMODEL  512
#define NHEADS  8
#define HDIM    64
#define DFF     2048
#define NLAYERS 6
#define MROWS   (BATCH * SEQ)            // 8192

// -------- scratch (device globals; no allocation allowed) --------
__device__ float    g_x   [MROWS * DMODEL];     // fp32 residual stream
__device__ uint32_t g_xh  [MROWS * DMODEL / 2]; // half2-packed x (gemm A)
__device__ uint32_t g_qh  [MROWS * DMODEL / 2]; // q half2-packed (d-pairs)
__device__ uint32_t g_kh  [MROWS * DMODEL / 2]; // k half2-packed (d-pairs)
__device__ float    g_v   [MROWS * DMODEL];     // v fp32 (tf32-rounded)
__device__ uint32_t g_ath [MROWS * DMODEL / 2]; // attn out, half2 packed
__device__ float    g_tmp [MROWS * DMODEL];
__device__ uint32_t g_ffh [MROWS * DFF / 2];    // ff out, half2 packed
// half2-packed weights: word(k',n) = (W[2k'][n], W[2k'+1][n])
#define WH_TOTAL 9437184
__device__ uint32_t g_wh  [WH_TOTAL];

// ==================== helpers ====================
__device__ __forceinline__ uint32_t f2tf32(float x) {
    uint32_t u;
    asm("cvt.rna.tf32.f32 %0, %1;" : "=r"(u) : "f"(x));
    return u;
}
__device__ __forceinline__ float rnd_tf32(float x) {
    return __uint_as_float(f2tf32(x));
}
__device__ __forceinline__ uint32_t packh2(float a, float b) {
    __half2 h = __floats2half2_rn(a, b);
    return *reinterpret_cast<uint32_t*>(&h);
}
__device__ __forceinline__ uint32_t smem_u32(const void* p) {
    uint32_t a;
    asm("{ .reg .u64 t; cvta.to.shared.u64 t, %1; cvt.u32.u64 %0, t; }"
        : "=r"(a) : "l"(p));
    return a;
}
__device__ __forceinline__ void cp16(uint32_t dst, const void* src) {
    asm volatile("cp.async.cg.shared.global [%0], [%1], 16;"
                 :: "r"(dst), "l"(src));
}
#define CP_COMMIT() asm volatile("cp.async.commit_group;" ::: "memory")
#define CP_WAIT0()  asm volatile("cp.async.wait_group 0;" ::: "memory")
#define CP_WAIT1()  asm volatile("cp.async.wait_group 1;" ::: "memory")

// mma m16n8k16 f16 inputs, f32 accum
__device__ __forceinline__ void mma_f16(
    float* d, const uint32_t* a, const uint32_t* b, const float* c)
{
    asm volatile(
        "mma.sync.aligned.m16n8k16.row.col.f32.f16.f16.f32 "
        "{%0,%1,%2,%3}, {%4,%5,%6,%7}, {%8,%9}, {%10,%11,%12,%13};"
        : "=f"(d[0]), "=f"(d[1]), "=f"(d[2]), "=f"(d[3])
        : "r"(a[0]), "r"(a[1]), "r"(a[2]), "r"(a[3]),
          "r"(b[0]), "r"(b[1]),
          "f"(c[0]), "f"(c[1]), "f"(c[2]), "f"(c[3]));
}
// mma m16n8k8 tf32 (attention PV)
__device__ __forceinline__ void mma_tf32(
    float* d, const uint32_t* a, const uint32_t* b, const float* c)
{
    asm volatile(
        "mma.sync.aligned.m16n8k8.row.col.f32.tf32.tf32.f32 "
        "{%0,%1,%2,%3}, {%4,%5,%6,%7}, {%8,%9}, {%10,%11,%12,%13};"
        : "=f"(d[0]), "=f"(d[1]), "=f"(d[2]), "=f"(d[3])
        : "r"(a[0]), "r"(a[1]), "r"(a[2]), "r"(a[3]),
          "r"(b[0]), "r"(b[1]),
          "f"(c[0]), "f"(c[1]), "f"(c[2]), "f"(c[3]));
}

// =====================================================================
// Weight packing: fp32 [K][N] -> half2 words [K/2][N]
// =====================================================================
__global__ void __launch_bounds__(256) pack_kernel(
    const float* __restrict__ s0, const float* __restrict__ s1,
    const float* __restrict__ s2, const float* __restrict__ s3,
    const float* __restrict__ s4, const float* __restrict__ s5,
    uint32_t* __restrict__ wh)
{
    int t = blockIdx.z;
    const float* s;
    if (t == 0) s = s0; else if (t == 1) s = s1; else if (t == 2) s = s2;
    else if (t == 3) s = s3; else if (t == 4) s = s4; else s = s5;
    int K = (t == 5) ? DFF : DMODEL;
    int N = (t == 4) ? DFF : DMODEL;
    int wpl = (K >> 1) * N;
    const size_t seg[6] = {0, 786432, 1572864, 2359296, 3145728, 6291456};
    int w = (blockIdx.x * 256 + threadIdx.x) * 4;
    if (w >= wpl) return;
    int kp = w / N, n = w % N;
    const float* sl = s + (size_t)blockIdx.y * K * N;
    float4 lo = *(const float4*)(sl + (size_t)(2 * kp) * N + n);
    float4 hi = *(const float4*)(sl + (size_t)(2 * kp + 1) * N + n);
    uint4 o = make_uint4(packh2(lo.x, hi.x), packh2(lo.y, hi.y),
                         packh2(lo.z, hi.z), packh2(lo.w, hi.w));
    *(uint4*)(wh + seg[t] + (size_t)blockIdx.y * wpl + w) = o;
}

// =====================================================================
// Embedding + positional encoding: dual write (fp32 + half2)
// =====================================================================
__global__ void __launch_bounds__(128) embed_kernel(
    const int* __restrict__ src, const float* __restrict__ emb,
    const float* __restrict__ pe, float* __restrict__ xf,
    uint32_t* __restrict__ xh)
{
    int bl  = blockIdx.x;
    int l   = bl & (SEQ - 1);
    int tok = src[bl];
    int c   = threadIdx.x * 4;
    float4 e = *(const float4*)(emb + (size_t)tok * DMODEL + c);
    float4 p = *(const float4*)(pe  + (size_t)l   * DMODEL + c);
    float4 o; o.x = e.x + p.x; o.y = e.y + p.y; o.z = e.z + p.z; o.w = e.w + p.w;
    *(float4*)(xf + (size_t)bl * DMODEL + c) = o;
    uint2 h = make_uint2(packh2(o.x, o.y), packh2(o.z, o.w));
    *(uint2*)(xh + (size_t)bl * (DMODEL / 2) + threadIdx.x * 2) = h;
}

// =====================================================================
// fp16 tensor-core GEMM: C = A@W + bias (+res)(+relu), out fp32 or half2
// =====================================================================
#define AWH    20
#define BWH    136
#define A_STGH (128 * AWH)
#define B_STGH (16 * BWH)
#define STG_WH (A_STGH + B_STGH)
#define GSH_SMEM (3 * STG_WH * 4)         // 56832 bytes

__device__ __forceinline__ void gemm_body(
    const uint32_t* __restrict__ A, const uint32_t* __restrict__ Wh,
    const float* __restrict__ bias, const float* __restrict__ res,
    float* __restrict__ Cf, uint32_t* __restrict__ Ch,
    int M, int N, int K, int relu, int rnd, int bxx, int byy)
{
    extern __shared__ uint32_t sm[];
    uint32_t sbase = smem_u32(sm);

    int tid  = threadIdx.x;
    int lane = tid & 31;
    int wid  = tid >> 5;
    int bm = byy << 7, bn = bxx << 7;
    int warpM = (wid >> 2) * 64;
    int warpN = (wid & 3) * 32;
    int r0 = lane >> 2, c0 = lane & 3;
    int K2 = K >> 1;

    float acc[4][4][4];
#pragma unroll
    for (int mt = 0; mt < 4; mt++)
#pragma unroll
        for (int nt = 0; nt < 4; nt++)
#pragma unroll
            for (int r = 0; r < 4; r++) acc[mt][nt][r] = 0.f;

    int nst = K >> 5;

    auto issue_stage = [&](int st, int kc2) {
        uint32_t aB = sbase + (st * STG_WH) * 4;
        uint32_t bB = sbase + (st * STG_WH + A_STGH) * 4;
#pragma unroll
        for (int i = 0; i < 2; i++) {
            int id = tid + i * 256;
            int row = id >> 2, c16 = id & 3;
            cp16(aB + (row * AWH + c16 * 4) * 4,
                 A + (size_t)row * K2 + kc2 + c16 * 4);
        }
#pragma unroll
        for (int i = 0; i < 2; i++) {
            int id = tid + i * 256;
            int kr = id >> 5, c16 = id & 31;
            cp16(bB + (kr * BWH + c16 * 4) * 4,
                 Wh + (size_t)(kc2 + kr) * N + bn + c16 * 4);
        }
        CP_COMMIT();
    };

    const uint32_t* Abase = A + (size_t)bm * K2;
    A = Abase;

    issue_stage(0, 0);
    issue_stage(1, 16);

    for (int s = 0; s < nst; s++) {
        int cur = s % 3;
        if (s + 1 < nst) CP_WAIT1(); else CP_WAIT0();
        __syncthreads();
        if (s + 2 < nst) issue_stage((s + 2) % 3, (s + 2) * 16);

        const uint32_t* Ab = sm + cur * STG_WH;
        const uint32_t* Bb = Ab + A_STGH;
#pragma unroll
        for (int ks = 0; ks < 2; ks++) {
            int kb = ks * 8;
            uint32_t af[4][4], bf[4][2];
#pragma unroll
            for (int mt = 0; mt < 4; mt++) {
                int m0 = warpM + mt * 16 + r0;
                af[mt][0] = Ab[m0 * AWH + kb + c0];
                af[mt][1] = Ab[(m0 + 8) * AWH + kb + c0];
                af[mt][2] = Ab[m0 * AWH + kb + c0 + 4];
                af[mt][3] = Ab[(m0 + 8) * AWH + kb + c0 + 4];
            }
#pragma unroll
            for (int nt = 0; nt < 4; nt++) {
                int n0 = warpN + nt * 8 + r0;
                bf[nt][0] = Bb[(kb + c0) * BWH + n0];
                bf[nt][1] = Bb[(kb + c0 + 4) * BWH + n0];
            }
#pragma unroll
            for (int mt = 0; mt < 4; mt++)
#pragma unroll
                for (int nt = 0; nt < 4; nt++)
                    mma_f16(acc[mt][nt], af[mt], bf[nt], acc[mt][nt]);
        }
        __syncthreads();
    }

#pragma unroll
    for (int mt = 0; mt < 4; mt++) {
        int row0 = bm + warpM + mt * 16 + r0;
#pragma unroll
        for (int h = 0; h < 2; h++) {
            int row = row0 + h * 8;
            const float* rrow = res ? (res + (size_t)row * N) : nullptr;
#pragma unroll
            for (int nt = 0; nt < 4; nt++) {
                int col = bn + warpN + nt * 8 + 2 * c0;
                float2 b2 = *(const float2*)(bias + col);
                float2 o;
                o.x = acc[mt][nt][h * 2 + 0] + b2.x;
                o.y = acc[mt][nt][h * 2 + 1] + b2.y;
                if (rrow) {
                    float2 r2 = *(const float2*)(rrow + col);
                    o.x += r2.x; o.y += r2.y;
                }
                if (relu) { o.x = fmaxf(o.x, 0.f); o.y = fmaxf(o.y, 0.f); }
                if (Ch) {
                    Ch[(size_t)row * (N >> 1) + (col >> 1)] = packh2(o.x, o.y);
                } else {
                    if (rnd) { o.x = rnd_tf32(o.x); o.y = rnd_tf32(o.y); }
                    *(float2*)(Cf + (size_t)row * N + col) = o;
                }
            }
        }
    }
}

__global__ void __launch_bounds__(256, 2) gemm_mma(
    const uint32_t* __restrict__ A, const uint32_t* __restrict__ Wh,
    const float* __restrict__ bias, const float* __restrict__ res,
    float* __restrict__ Cf, uint32_t* __restrict__ Ch,
    int M, int N, int K, int relu, int rnd)
{
    gemm_body(A, Wh, bias, res, Cf, Ch, M, N, K, relu, rnd,
              blockIdx.x, blockIdx.y);
}

// fused QKV: q,k written half2-packed (attention S is fp16); v fp32 tf32
__global__ void __launch_bounds__(256, 2) gemm_qkv(
    const uint32_t* __restrict__ x,
    const uint32_t* __restrict__ Wq, const uint32_t* __restrict__ Wk,
    const uint32_t* __restrict__ Wv,
    const float* __restrict__ bq, const float* __restrict__ bk,
    const float* __restrict__ bv,
    uint32_t* __restrict__ qh, uint32_t* __restrict__ kh,
    float* __restrict__ v)
{
    const uint32_t* W; const float* bias; float* Cf; uint32_t* Ch;
    if (blockIdx.z == 0)      { W = Wq; bias = bq; Cf = nullptr; Ch = qh; }
    else if (blockIdx.z == 1) { W = Wk; bias = bk; Cf = nullptr; Ch = kh; }
    else                      { W = Wv; bias = bv; Cf = v; Ch = nullptr; }
    gemm_body(x, W, bias, nullptr, Cf, Ch, MROWS, DMODEL, DMODEL, 0, 1,
              blockIdx.x, blockIdx.y);
}

// =====================================================================
// Flash attention: S phase fp16 (q/k half2-packed along d), softmax +
// PV tf32 (register P, permuted V reads) — round-16 pipeline otherwise.
// smem words: K0[0,2304) V0[2304,6656) K1[6656,8960) V1[8960,13312)
// K tile: 64 x 32 packed words, stride 36 (conflict-free).
// =====================================================================
#define ATS 68
#define KST 36
#define KTW (64 * KST)                    // 2304 words
#define VTW (64 * ATS)                    // 4352 words
#define ATTNH_SMEM ((2 * KTW + 2 * VTW) * 4)   // 53248 bytes

__device__ __forceinline__ void cp_tile_v(
    uint32_t dstbase, const float* __restrict__ g, int tid)
{
#pragma unroll
    for (int i = 0; i < 8; i++) {
        int id  = tid + i * 128;
        int row = id >> 4, c16 = id & 15;
        cp16(dstbase + (row * ATS + c16 * 4) * 4, g + row * 64 + c16 * 4);
    }
}
__device__ __forceinline__ void cp_tile_k(
    uint32_t dstbase, const uint32_t* __restrict__ g, int tid)
{
#pragma unroll
    for (int i = 0; i < 4; i++) {
        int id  = tid + i * 128;
        int row = id >> 3, c16 = id & 7;
        cp16(dstbase + (row * KST + c16 * 4) * 4, g + row * 32 + c16 * 4);
    }
}

__global__ void __launch_bounds__(128, 3) attn_mma(
    const uint32_t* __restrict__ qh, const uint32_t* __restrict__ kh,
    const float* __restrict__ v, uint32_t* __restrict__ outh)
{
    extern __shared__ uint32_t smu[];
    uint32_t sbase = smem_u32(smu);

    int tid  = threadIdx.x;
    int lane = tid & 31;
    int wid  = tid >> 5;
    int bh   = blockIdx.y;
    int qt   = blockIdx.x;
    int b    = bh >> 3, h = bh & 7;

    const uint32_t* Qg = qh + ((size_t)bh * SEQ + qt * 64) * (HDIM / 2);
    const uint32_t* Kg = kh + (size_t)bh * SEQ * (HDIM / 2);
    const float*    Vg = v  + (size_t)bh * SEQ * HDIM;

    cp_tile_k(sbase + 0 * KTW * 4, Kg, tid);
    cp_tile_v(sbase + 1 * KTW * 4, Vg, tid);
    CP_COMMIT();

    int warpM = wid * 16;
    int r0 = lane >> 2, c0 = lane & 3;

    // Q fragments from gmem, half2-packed (4 k16 steps x 4 regs)
    uint32_t qf[4][4];
#pragma unroll
    for (int ks = 0; ks < 4; ks++) {
        int kk = ks * 8 + c0;
        qf[ks][0] = Qg[(warpM + r0) * (HDIM / 2) + kk];
        qf[ks][1] = Qg[(warpM + r0 + 8) * (HDIM / 2) + kk];
        qf[ks][2] = Qg[(warpM + r0) * (HDIM / 2) + kk + 4];
        qf[ks][3] = Qg[(warpM + r0 + 8) * (HDIM / 2) + kk + 4];
    }

    float m0 = -1e30f, m1 = -1e30f, l0 = 0.f, l1 = 0.f;
    float o_acc[8][4];
#pragma unroll
    for (int nt = 0; nt < 8; nt++)
#pragma unroll
        for (int r = 0; r < 4; r++) o_acc[nt][r] = 0.f;

    for (int kt = 0; kt < SEQ / 64; kt++) {
        int cur = kt & 1, nb = cur ^ 1;
        CP_WAIT0();
        __syncthreads();
        if (kt + 1 < SEQ / 64) {
            cp_tile_k(sbase + (nb * (KTW + VTW)) * 4 + 0,
                      Kg + (size_t)(kt + 1) * 64 * (HDIM / 2), tid);
            cp_tile_v(sbase + (nb * (KTW + VTW) + KTW) * 4,
                      Vg + (size_t)(kt + 1) * 64 * HDIM, tid);
            CP_COMMIT();
        }
        const uint32_t* Ks = smu + cur * (KTW + VTW);
        const uint32_t* Vs = Ks + KTW;

        // ---- S = Q K^T, fp16 m16n8k16 ----
        float sacc[8][4];
#pragma unroll
        for (int nt = 0; nt < 8; nt++)
#pragma unroll
            for (int r = 0; r < 4; r++) sacc[nt][r] = 0.f;

#pragma unroll
        for (int ks = 0; ks < 4; ks++) {
            int kk = ks * 8 + c0;
#pragma unroll
            for (int nt = 0; nt < 8; nt++) {
                uint32_t bb[2];
                bb[0] = Ks[(nt * 8 + r0) * KST + kk];
                bb[1] = Ks[(nt * 8 + r0) * KST + kk + 4];
                mma_f16(sacc[nt], qf[ks], bb, sacc[nt]);
            }
        }

        // ---- online softmax ----
        float mt0 = -1e30f, mt1 = -1e30f;
#pragma unroll
        for (int nt = 0; nt < 8; nt++) {
#pragma unroll
            for (int r = 0; r < 4; r++) sacc[nt][r] *= 0.125f;
            mt0 = fmaxf(mt0, fmaxf(sacc[nt][0], sacc[nt][1]));
            mt1 = fmaxf(mt1, fmaxf(sacc[nt][2], sacc[nt][3]));
        }
        mt0 = fmaxf(mt0, __shfl_xor_sync(0xffffffffu, mt0, 1));
        mt0 = fmaxf(mt0, __shfl_xor_sync(0xffffffffu, mt0, 2));
        mt1 = fmaxf(mt1, __shfl_xor_sync(0xffffffffu, mt1, 1));
        mt1 = fmaxf(mt1, __shfl_xor_sync(0xffffffffu, mt1, 2));

        float mn0 = fmaxf(m0, mt0), mn1 = fmaxf(m1, mt1);
        float corr0 = __expf(m0 - mn0), corr1 = __expf(m1 - mn1);
        m0 = mn0; m1 = mn1;

        uint32_t pf[8][4];
        float rs0 = 0.f, rs1 = 0.f;
#pragma unroll
        for (int nt = 0; nt < 8; nt++) {
            float p00 = __expf(sacc[nt][0] - mn0);
            float p01 = __expf(sacc[nt][1] - mn0);
            float p10 = __expf(sacc[nt][2] - mn1);
            float p11 = __expf(sacc[nt][3] - mn1);
            rs0 += p00 + p01; rs1 += p10 + p11;
            pf[nt][0] = f2tf32(p00);
            pf[nt][1] = f2tf32(p10);
            pf[nt][2] = f2tf32(p01);
            pf[nt][3] = f2tf32(p11);
        }
        rs0 += __shfl_xor_sync(0xffffffffu, rs0, 1);
        rs0 += __shfl_xor_sync(0xffffffffu, rs0, 2);
        rs1 += __shfl_xor_sync(0xffffffffu, rs1, 1);
        rs1 += __shfl_xor_sync(0xffffffffu, rs1, 2);
        l0 = l0 * corr0 + rs0;
        l1 = l1 * corr1 + rs1;

#pragma unroll
        for (int nt = 0; nt < 8; nt++) {
            o_acc[nt][0] *= corr0; o_acc[nt][1] *= corr0;
            o_acc[nt][2] *= corr1; o_acc[nt][3] *= corr1;
        }

        // ---- O += P @ V (tf32; P registers, V rows permuted) ----
#pragma unroll
        for (int ks = 0; ks < 8; ks++) {
            int kk = ks * 8;
#pragma unroll
            for (int nt = 0; nt < 8; nt++) {
                uint32_t bb[2];
                bb[0] = Vs[(kk + 2 * c0) * ATS + nt * 8 + r0];
                bb[1] = Vs[(kk + 2 * c0 + 1) * ATS + nt * 8 + r0];
                mma_tf32(o_acc[nt], pf[ks], bb, o_acc[nt]);
            }
        }
    }

    // epilogue: /l, pack half2, scatter to [B, L, (H*64+d)/2]
    float inv0 = 1.0f / l0, inv1 = 1.0f / l1;
    size_t row0 = (size_t)b * SEQ + qt * 64 + warpM + r0;
    uint32_t* O0 = outh + row0 * (DMODEL / 2) + h * (HDIM / 2);
    uint32_t* O1 = O0 + 8 * (DMODEL / 2);
#pragma unroll
    for (int nt = 0; nt < 8; nt++) {
        int w = nt * 4 + c0;
        O0[w] = packh2(o_acc[nt][0] * inv0, o_acc[nt][1] * inv0);
        O1[w] = packh2(o_acc[nt][2] * inv1, o_acc[nt][3] * inv1);
    }
}

// =====================================================================
// LayerNorm over last dim (512). Dual write (fp32 + half2).
// =====================================================================
__global__ void __launch_bounds__(128) ln_kernel(
    const float* __restrict__ in, const float* __restrict__ g,
    const float* __restrict__ b, float* __restrict__ out_f,
    uint32_t* __restrict__ out_h)
{
    int row = blockIdx.x;
    int tid = threadIdx.x;
    float4 v4 = *(const float4*)(in + (size_t)row * DMODEL + tid * 4);
    float s  = v4.x + v4.y + v4.z + v4.w;
    float sq = v4.x * v4.x + v4.y * v4.y + v4.z * v4.z + v4.w * v4.w;
#pragma unroll
    for (int off = 16; off > 0; off >>= 1) {
        s  += __shfl_xor_sync(0xffffffffu, s, off);
        sq += __shfl_xor_sync(0xffffffffu, sq, off);
    }
    __shared__ float ss[4], sqs[4];
    int wid = tid >> 5;
    if ((tid & 31) == 0) { ss[wid] = s; sqs[wid] = sq; }
    __syncthreads();
    s  = ss[0] + ss[1] + ss[2] + ss[3];
    sq = sqs[0] + sqs[1] + sqs[2] + sqs[3];
    float mu  = s * (1.0f / DMODEL);
    float var = sq * (1.0f / DMODEL) - mu * mu;
    float inv = rsqrtf(var + 1e-5f);
    float4 gv = *(const float4*)(g + tid * 4);
    float4 bv = *(const float4*)(b + tid * 4);
    float4 o;
    o.x = (v4.x - mu) * inv * gv.x + bv.x;
    o.y = (v4.y - mu) * inv * gv.y + bv.y;
    o.z = (v4.z - mu) * inv * gv.z + bv.z;
    o.w = (v4.w - mu) * inv * gv.w + bv.w;
    *(float4*)(out_f + (size_t)row * DMODEL + tid * 4) = o;
    if (out_h) {
        uint2 hw = make_uint2(packh2(o.x, o.y), packh2(o.z, o.w));
        *(uint2*)(out_h + (size_t)row * (DMODEL / 2) + tid * 2) = hw;
    }
}

// =====================================================================
// host launcher
// =====================================================================
extern "C" void kernel_launch(void* const* d_in, const int* in_sizes, int n_in,
                              void* d_out, int out_size)
{
    const int*   src  = (const int*)  d_in[0];
    const float* emb  = (const float*)d_in[1];
    const float* pe   = (const float*)d_in[2];
    const float* Wq   = (const float*)d_in[3];
    const float* bq   = (const float*)d_in[4];
    const float* Wk   = (const float*)d_in[5];
    const float* bk   = (const float*)d_in[6];
    const float* Wv   = (const float*)d_in[7];
    const float* bv   = (const float*)d_in[8];
    const float* Wo   = (const float*)d_in[9];
    const float* bo   = (const float*)d_in[10];
    const float* W1   = (const float*)d_in[11];
    const float* b1   = (const float*)d_in[12];
    const float* W2   = (const float*)d_in[13];
    const float* b2   = (const float*)d_in[14];
    const float* g1   = (const float*)d_in[15];
    const float* be1  = (const float*)d_in[16];
    const float* g2   = (const float*)d_in[17];
    const float* be2  = (const float*)d_in[18];
    float* outp = (float*)d_out;

    float *x, *v, *tmp;
    uint32_t *xh, *qh, *kh, *ath, *ffh, *wh;
    cudaGetSymbolAddress((void**)&x,    g_x);
    cudaGetSymbolAddress((void**)&xh,   g_xh);
    cudaGetSymbolAddress((void**)&qh,   g_qh);
    cudaGetSymbolAddress((void**)&kh,   g_kh);
    cudaGetSymbolAddress((void**)&v,    g_v);
    cudaGetSymbolAddress((void**)&ath,  g_ath);
    cudaGetSymbolAddress((void**)&tmp,  g_tmp);
    cudaGetSymbolAddress((void**)&ffh,  g_ffh);
    cudaGetSymbolAddress((void**)&wh,   g_wh);

    cudaFuncSetAttribute(attn_mma,
                         cudaFuncAttributeMaxDynamicSharedMemorySize, ATTNH_SMEM);
    cudaFuncSetAttribute(gemm_mma,
                         cudaFuncAttributeMaxDynamicSharedMemorySize, GSH_SMEM);
    cudaFuncSetAttribute(gemm_qkv,
                         cudaFuncAttributeMaxDynamicSharedMemorySize, GSH_SMEM);

    uint32_t* WqH = wh;
    uint32_t* WkH = wh + 786432;
    uint32_t* WvH = wh + 1572864;
    uint32_t* WoH = wh + 2359296;
    uint32_t* W1H = wh + 3145728;
    uint32_t* W2H = wh + 6291456;
    const size_t wplD = 131072;
    const size_t wplF = 524288;

    pack_kernel<<<dim3(512, NLAYERS, 6), 256>>>(Wq, Wk, Wv, Wo, W1, W2, wh);

    embed_kernel<<<MROWS, 128>>>(src, emb, pe, x, xh);

    dim3 gQKV(DMODEL / 128, MROWS / 128, 3);
    dim3 gProj(DMODEL / 128, MROWS / 128);
    dim3 gFF1(DFF / 128,    MROWS / 128);
    dim3 gAttn(SEQ / 64, BATCH * NHEADS);

    for (int L = 0; L < NLAYERS; L++) {
        const size_t vd  = (size_t)L * DMODEL;
        const size_t vf  = (size_t)L * DFF;

        gemm_qkv<<<gQKV, 256, GSH_SMEM>>>(xh, WqH + L * wplD, WkH + L * wplD,
                                          WvH + L * wplD,
                                          bq + vd, bk + vd, bv + vd,
                                          qh, kh, v);

        attn_mma<<<gAttn, 128, ATTNH_SMEM>>>(qh, kh, v, ath);

        gemm_mma<<<gProj, 256, GSH_SMEM>>>(ath, WoH + L * wplD, bo + vd, x,
                                           tmp, nullptr,
                                           MROWS, DMODEL, DMODEL, 0, 0);
        ln_kernel<<<MROWS, 128>>>(tmp, g1 + vd, be1 + vd, x, xh);

        gemm_mma<<<gFF1, 256, GSH_SMEM>>>(xh, W1H + L * wplF, b1 + vf, nullptr,
                                          nullptr, ffh,
                                          MROWS, DFF, DMODEL, 1, 0);
        gemm_mma<<<gProj, 256, GSH_SMEM>>>(ffh, W2H + L * wplF, b2 + vd, x,
                                           tmp, nullptr,
                                           MROWS, DMODEL, DFF, 0, 0);
        ln_kernel<<<MROWS, 128>>>(tmp, g2 + vd, be2 + vd,
                                  (L == NLAYERS - 1) ? outp : x,
                                  (L == NLAYERS - 1) ? nullptr : xh);
    }
}